// round 2
// baseline (speedup 1.0000x reference)
#include <cuda_runtime.h>
#include <cstdint>

// Problem constants
#define B_DIM 16
#define C_DIM 64
#define K_DIM 207
#define L_DIM 64
#define KL    13248        // K_DIM * L_DIM
#define C_IN  320

// Scratch (device globals per harness rules — no cudaMalloc allowed)
__device__ float g_Asq[2 * B_DIM * K_DIM * K_DIM];                 // A0^2, A1^2 (~5.5 MB)
__device__ float g_U[(size_t)B_DIM * 4 * C_DIM * KL];              // U_t, t=1..4 (~217 MB)

// ---------------------------------------------------------------------------
// packed fp32x2 helpers (ptxas will not auto-fuse FFMA2; must come from PTX)
// ---------------------------------------------------------------------------
__device__ __forceinline__ unsigned long long ffma2(unsigned long long a,
                                                    unsigned long long b,
                                                    unsigned long long c) {
    unsigned long long d;
    asm("fma.rn.f32x2 %0, %1, %2, %3;" : "=l"(d) : "l"(a), "l"(b), "l"(c));
    return d;
}
__device__ __forceinline__ unsigned long long pack2(float x) {
    unsigned long long d;
    asm("mov.b64 %0, {%1, %1};" : "=l"(d) : "r"(__float_as_uint(x)));
    return d;
}
__device__ __forceinline__ float2 unpack2(unsigned long long v) {
    float2 f;
    asm("mov.b64 {%0, %1}, %2;" : "=f"(f.x), "=f"(f.y) : "l"(v));
    return f;
}

// ---------------------------------------------------------------------------
// Kernel A: per-batch adjacency squares  B = A @ A  (207x207) — negligible cost
// ---------------------------------------------------------------------------
__global__ void square_kernel(const float* __restrict__ a0,
                              const float* __restrict__ a1) {
    const int z     = blockIdx.z;       // 0..31
    const int which = z & 1;
    const int b     = z >> 1;
    const float* A  = (which == 0 ? a0 : a1) + (size_t)b * K_DIM * K_DIM;
    float* O        = g_Asq + (size_t)(which * B_DIM + b) * K_DIM * K_DIM;

    const int j = blockIdx.y * 16 + threadIdx.y;
    const int k = blockIdx.x * 16 + threadIdx.x;

    __shared__ float As[16][17];
    __shared__ float Bs[16][17];

    float s = 0.f;
    for (int m0 = 0; m0 < K_DIM; m0 += 16) {
        const int mA = m0 + threadIdx.x;
        const int mB = m0 + threadIdx.y;
        As[threadIdx.y][threadIdx.x] = (j < K_DIM && mA < K_DIM) ? A[(size_t)j * K_DIM + mA] : 0.f;
        Bs[threadIdx.y][threadIdx.x] = (mB < K_DIM && k < K_DIM) ? A[(size_t)mB * K_DIM + k] : 0.f;
        __syncthreads();
        #pragma unroll
        for (int mm = 0; mm < 16; ++mm)
            s += As[threadIdx.y][mm] * Bs[mm][threadIdx.x];
        __syncthreads();
    }
    if (j < K_DIM && k < K_DIM) O[(size_t)j * K_DIM + k] = s;
}

// ---------------------------------------------------------------------------
// Kernel B: channel-mix  U_t[o,k,l] = sum_c W[o, t*64+c] * x[b,c,k,l]
//   t = 0: writes W0*x + bias directly into out (the self term)
//   t = 1..4: writes into g_U block (t-1)
// Tile: 64 (i=o) x 256 (n=(k,l)), inner C=64 in chunks of 32. 256 thr, 8x8 micro.
// ---------------------------------------------------------------------------
__global__ __launch_bounds__(256, 2)
void chanmix_kernel(const float* __restrict__ x, const float* __restrict__ W,
                    const float* __restrict__ bias, float* __restrict__ out) {
    const int b     = blockIdx.z;
    const int t     = blockIdx.y;              // 0..4
    const int nbase = blockIdx.x * 256;        // 52 tiles, last ragged
    const int tid   = threadIdx.x;
    const int tx    = tid & 31;                // n dim (32 threads)
    const int ty    = tid >> 5;                // i dim (8 threads)

    __shared__ __align__(16) float As[64][33];   // [ii][kk]
    __shared__ __align__(16) float Us[32][260];  // [kk][c]

    unsigned long long acc[8][4];
    #pragma unroll
    for (int i = 0; i < 8; ++i)
        #pragma unroll
        for (int p = 0; p < 4; ++p) acc[i][p] = 0ull;

    const float* xb = x + (size_t)b * C_DIM * KL;

    for (int c0 = 0; c0 < 64; c0 += 32) {
        // load W tile: As[ii][kk] = W[ii*320 + t*64 + c0 + kk]
        #pragma unroll
        for (int it = 0; it < 8; ++it) {
            int e = tid + it * 256;
            int ii = e >> 5, kk = e & 31;
            As[ii][kk] = W[(size_t)ii * C_IN + t * 64 + c0 + kk];
        }
        // load x tile: Us[kk][c] = x[b][c0+kk][nbase+c]
        #pragma unroll
        for (int it = 0; it < 32; ++it) {
            int e = tid + it * 256;
            int kk = e >> 8, c = e & 255;
            int n = nbase + c;
            Us[kk][c] = (n < KL) ? xb[(size_t)(c0 + kk) * KL + n] : 0.f;
        }
        __syncthreads();

        #pragma unroll 4
        for (int kk = 0; kk < 32; ++kk) {
            const ulonglong2 ua = *(const ulonglong2*)&Us[kk][4 * tx];
            const ulonglong2 ub = *(const ulonglong2*)&Us[kk][128 + 4 * tx];
            #pragma unroll
            for (int i = 0; i < 8; ++i) {
                const int jj = (i < 4) ? (4 * ty + i) : (32 + 4 * ty + (i - 4));
                const unsigned long long a2 = pack2(As[jj][kk]);
                acc[i][0] = ffma2(a2, ua.x, acc[i][0]);
                acc[i][1] = ffma2(a2, ua.y, acc[i][1]);
                acc[i][2] = ffma2(a2, ub.x, acc[i][2]);
                acc[i][3] = ffma2(a2, ub.y, acc[i][3]);
            }
        }
        __syncthreads();
    }

    // store: t=0 -> out (+bias), t>=1 -> g_U block (t-1)
    float* Ub = (t == 0)
        ? out + (size_t)b * C_DIM * KL
        : g_U + (((size_t)b * 4 + (t - 1)) * C_DIM) * KL;
    #pragma unroll
    for (int i = 0; i < 8; ++i) {
        const int ii = (i < 4) ? (4 * ty + i) : (32 + 4 * ty + (i - 4));
        const float bo = (t == 0) ? bias[ii] : 0.f;
        #pragma unroll
        for (int h = 0; h < 2; ++h) {
            const int c = h * 128 + 4 * tx;
            const int n = nbase + c;
            if (n < KL) {
                const float2 p0 = unpack2(acc[i][2 * h + 0]);
                const float2 p1 = unpack2(acc[i][2 * h + 1]);
                float4 r = make_float4(p0.x + bo, p0.y + bo, p1.x + bo, p1.y + bo);
                *(float4*)&Ub[(size_t)ii * KL + n] = r;
            }
        }
    }
}

// ---------------------------------------------------------------------------
// Kernel C: diffusion + accumulate into out:
//   out[b,o,j,l] += sum_{t=1..4} sum_k M_t[j,k] U_t[o,k,l]
// Tile: 64 (j) x 256 (n = 4 o's x 64 l), inner 4x207 in chunks of 32.
// Tiles are disjoint; out already holds W0*x + bias from kernel B.
// ---------------------------------------------------------------------------
__global__ __launch_bounds__(256, 2)
void diffuse_kernel(const float* __restrict__ a0, const float* __restrict__ a1,
                    float* __restrict__ out) {
    const int b   = blockIdx.z;
    const int o0  = blockIdx.x * 4;   // 16 o-tiles
    const int j0  = blockIdx.y * 64;  // 4 j-tiles
    const int tid = threadIdx.x;
    const int tx  = tid & 31;         // n dim
    const int ty  = tid >> 5;         // j dim

    __shared__ __align__(16) float As[64][33];   // [jj][kk]
    __shared__ __align__(16) float Us[32][260];  // [kk][c]

    unsigned long long acc[8][4];
    #pragma unroll
    for (int i = 0; i < 8; ++i)
        #pragma unroll
        for (int p = 0; p < 4; ++p) acc[i][p] = 0ull;

    for (int t = 1; t <= 4; ++t) {
        const float* Amat;
        if      (t == 1) Amat = a0 + (size_t)b * K_DIM * K_DIM;
        else if (t == 2) Amat = g_Asq + (size_t)(0 * B_DIM + b) * K_DIM * K_DIM;
        else if (t == 3) Amat = a1 + (size_t)b * K_DIM * K_DIM;
        else             Amat = g_Asq + (size_t)(1 * B_DIM + b) * K_DIM * K_DIM;
        const float* Ut = g_U + (((size_t)b * 4 + (t - 1)) * C_DIM + o0) * KL;

        for (int k0 = 0; k0 < K_DIM; k0 += 32) {
            // load A tile (zero-padded)
            #pragma unroll
            for (int it = 0; it < 8; ++it) {
                int e = tid + it * 256;
                int jj = e >> 5, kk = e & 31;
                int j = j0 + jj, k = k0 + kk;
                As[jj][kk] = (j < K_DIM && k < K_DIM) ? Amat[(size_t)j * K_DIM + k] : 0.f;
            }
            // load U tile (zero-padded on k)
            #pragma unroll
            for (int it = 0; it < 32; ++it) {
                int e = tid + it * 256;
                int kk = e >> 8, c = e & 255;
                int k = k0 + kk;
                int o_loc = c >> 6, l = c & 63;
                Us[kk][c] = (k < K_DIM) ? Ut[(size_t)o_loc * KL + (size_t)k * L_DIM + l] : 0.f;
            }
            __syncthreads();

            #pragma unroll 4
            for (int kk = 0; kk < 32; ++kk) {
                const ulonglong2 ua = *(const ulonglong2*)&Us[kk][4 * tx];
                const ulonglong2 ub = *(const ulonglong2*)&Us[kk][128 + 4 * tx];
                #pragma unroll
                for (int i = 0; i < 8; ++i) {
                    const int jj = (i < 4) ? (4 * ty + i) : (32 + 4 * ty + (i - 4));
                    const unsigned long long a2 = pack2(As[jj][kk]);
                    acc[i][0] = ffma2(a2, ua.x, acc[i][0]);
                    acc[i][1] = ffma2(a2, ua.y, acc[i][1]);
                    acc[i][2] = ffma2(a2, ub.x, acc[i][2]);
                    acc[i][3] = ffma2(a2, ub.y, acc[i][3]);
                }
            }
            __syncthreads();
        }
    }

    // epilogue: accumulate onto out tile (holds W0*x + bias)
    float* Ob = out + ((size_t)b * C_DIM + o0) * KL;
    #pragma unroll
    for (int i = 0; i < 8; ++i) {
        const int jj = (i < 4) ? (4 * ty + i) : (32 + 4 * ty + (i - 4));
        const int j = j0 + jj;
        if (j < K_DIM) {
            #pragma unroll
            for (int h = 0; h < 2; ++h) {
                const int c = h * 128 + 4 * tx;
                const int o_loc = c >> 6, l = c & 63;
                const float2 p0 = unpack2(acc[i][2 * h + 0]);
                const float2 p1 = unpack2(acc[i][2 * h + 1]);
                const size_t off = (size_t)o_loc * KL + (size_t)j * L_DIM + l;
                const float4 u0 = *(const float4*)&Ob[off];
                float4 r = make_float4(p0.x + u0.x, p0.y + u0.y,
                                       p1.x + u0.z, p1.y + u0.w);
                *(float4*)&Ob[off] = r;
            }
        }
    }
}

// ---------------------------------------------------------------------------
extern "C" void kernel_launch(void* const* d_in, const int* in_sizes, int n_in,
                              void* d_out, int out_size) {
    (void)in_sizes; (void)n_in; (void)out_size;
    const float* x    = (const float*)d_in[0];
    const float* a0   = (const float*)d_in[1];
    const float* a1   = (const float*)d_in[2];
    const float* W    = (const float*)d_in[3];
    const float* bias = (const float*)d_in[4];
    float* out        = (float*)d_out;

    // A: adjacency squares
    {
        dim3 grid((K_DIM + 15) / 16, (K_DIM + 15) / 16, 2 * B_DIM);
        dim3 block(16, 16);
        square_kernel<<<grid, block>>>(a0, a1);
    }
    // B: channel mix -> g_U (t=1..4) and out (t=0, +bias)
    {
        dim3 grid((KL + 255) / 256, 5, B_DIM);   // 52 x 5 x 16
        chanmix_kernel<<<grid, 256>>>(x, W, bias, out);
    }
    // C: diffusion, accumulate into out
    {
        dim3 grid(C_DIM / 4, (K_DIM + 63) / 64, B_DIM);  // 16 x 4 x 16
        diffuse_kernel<<<grid, 256>>>(a0, a1, out);
    }
}

// round 5
// speedup vs baseline: 1.0861x; 1.0861x over previous
#include <cuda_runtime.h>
#include <cstdint>

#define B_DIM 16
#define C_DIM 64
#define K_DIM 207
#define L_DIM 64
#define KL    13248
#define C_IN  320
#define KSQ   (K_DIM * K_DIM)

__device__ float g_Asq[2 * B_DIM * KSQ];
__device__ float g_U[(size_t)B_DIM * 4 * C_DIM * KL];

__device__ __forceinline__ unsigned long long ffma2(unsigned long long a,
                                                    unsigned long long b,
                                                    unsigned long long c) {
    unsigned long long d;
    asm("fma.rn.f32x2 %0, %1, %2, %3;" : "=l"(d) : "l"(a), "l"(b), "l"(c));
    return d;
}
__device__ __forceinline__ unsigned long long pack2(float x) {
    unsigned long long d;
    asm("mov.b64 %0, {%1, %1};" : "=l"(d) : "r"(__float_as_uint(x)));
    return d;
}
__device__ __forceinline__ float2 unpack2(unsigned long long v) {
    float2 f;
    asm("mov.b64 {%0, %1}, %2;" : "=f"(f.x), "=f"(f.y) : "l"(v));
    return f;
}

// ---------------------------------------------------------------------------
// Kernel A: per-batch A@A (207x207). 32x32 tiles, block(16,16), 2x2 micro.
// All shared indices <= 31 (tx,ty in 0..15; +16 stays in range).
// ---------------------------------------------------------------------------
__global__ __launch_bounds__(256)
void square_kernel(const float* __restrict__ a0, const float* __restrict__ a1) {
    const int z = blockIdx.z;
    const int which = z & 1, b = z >> 1;
    const float* A = (which == 0 ? a0 : a1) + (size_t)b * KSQ;
    float* O = g_Asq + (size_t)(which * B_DIM + b) * KSQ;

    const int tx = threadIdx.x;   // 0..15
    const int ty = threadIdx.y;   // 0..15
    const int tid = ty * 16 + tx; // 0..255
    const int j0 = blockIdx.y * 32, k0 = blockIdx.x * 32;

    __shared__ float As[32][33];
    __shared__ float Bs[32][33];

    float acc[2][2] = {{0.f, 0.f}, {0.f, 0.f}};
    for (int m0 = 0; m0 < K_DIM; m0 += 32) {
        #pragma unroll
        for (int q = 0; q < 4; ++q) {
            int e = tid + q * 256;      // 0..1023
            int r = e >> 5, cc = e & 31;
            int jA = j0 + r, mA = m0 + cc;
            As[r][cc] = (jA < K_DIM && mA < K_DIM) ? A[(size_t)jA * K_DIM + mA] : 0.f;
            int mB = m0 + r, kB = k0 + cc;
            Bs[r][cc] = (mB < K_DIM && kB < K_DIM) ? A[(size_t)mB * K_DIM + kB] : 0.f;
        }
        __syncthreads();
        #pragma unroll 8
        for (int mm = 0; mm < 32; ++mm) {
            float av0 = As[ty][mm], av1 = As[ty + 16][mm];
            float bv0 = Bs[mm][tx], bv1 = Bs[mm][tx + 16];
            acc[0][0] += av0 * bv0; acc[0][1] += av0 * bv1;
            acc[1][0] += av1 * bv0; acc[1][1] += av1 * bv1;
        }
        __syncthreads();
    }
    #pragma unroll
    for (int qi = 0; qi < 2; ++qi)
        #pragma unroll
        for (int qj = 0; qj < 2; ++qj) {
            int j = j0 + ty + qi * 16, k = k0 + tx + qj * 16;
            if (j < K_DIM && k < K_DIM) O[(size_t)j * K_DIM + k] = acc[qi][qj];
        }
}

// ---------------------------------------------------------------------------
// Kernel B: channel-mix. Tile 64(i) x 256(n), C=64 in chunks of 32.
// At stored transposed [kk][ii] -> A-fragment read is 2x LDS.128.
// ---------------------------------------------------------------------------
__global__ __launch_bounds__(256, 2)
void chanmix_kernel(const float* __restrict__ x, const float* __restrict__ W,
                    const float* __restrict__ bias, float* __restrict__ out) {
    const int b = blockIdx.z, t = blockIdx.y;
    const int nbase = blockIdx.x * 256;
    const int tid = threadIdx.x;
    const int tx = tid & 31, ty = tid >> 5;

    __shared__ __align__(16) float At[32][68];   // [kk][ii]
    __shared__ __align__(16) float Us[32][260];  // [kk][c]

    unsigned long long acc[8][4];
    #pragma unroll
    for (int i = 0; i < 8; ++i)
        #pragma unroll
        for (int p = 0; p < 4; ++p) acc[i][p] = 0ull;

    const float* xb = x + (size_t)b * C_DIM * KL;
    const float4 z4 = make_float4(0.f, 0.f, 0.f, 0.f);

    for (int c0 = 0; c0 < 64; c0 += 32) {
        #pragma unroll
        for (int it = 0; it < 8; ++it) {         // W tile (transposed store)
            int e = tid + it * 256;
            int ii = e >> 5, kk = e & 31;
            At[kk][ii] = W[(size_t)ii * C_IN + t * 64 + c0 + kk];
        }
        #pragma unroll
        for (int it = 0; it < 8; ++it) {         // x tile, float4
            int e = tid + it * 256;
            int kk = e >> 6, c = (e & 63) * 4;
            int n = nbase + c;
            float4 v = (n < KL) ? *(const float4*)&xb[(size_t)(c0 + kk) * KL + n] : z4;
            *(float4*)&Us[kk][c] = v;
        }
        __syncthreads();

        #pragma unroll 4
        for (int kk = 0; kk < 32; ++kk) {
            const float4 a0v = *(const float4*)&At[kk][4 * ty];
            const float4 a1v = *(const float4*)&At[kk][32 + 4 * ty];
            const ulonglong2 ua = *(const ulonglong2*)&Us[kk][4 * tx];
            const ulonglong2 ub = *(const ulonglong2*)&Us[kk][128 + 4 * tx];
            const float af[8] = {a0v.x, a0v.y, a0v.z, a0v.w, a1v.x, a1v.y, a1v.z, a1v.w};
            #pragma unroll
            for (int i = 0; i < 8; ++i) {
                const unsigned long long a2 = pack2(af[i]);
                acc[i][0] = ffma2(a2, ua.x, acc[i][0]);
                acc[i][1] = ffma2(a2, ua.y, acc[i][1]);
                acc[i][2] = ffma2(a2, ub.x, acc[i][2]);
                acc[i][3] = ffma2(a2, ub.y, acc[i][3]);
            }
        }
        __syncthreads();
    }

    float* Ub = (t == 0)
        ? out + (size_t)b * C_DIM * KL
        : g_U + (((size_t)b * 4 + (t - 1)) * C_DIM) * KL;
    #pragma unroll
    for (int i = 0; i < 8; ++i) {
        const int ii = (i < 4) ? (4 * ty + i) : (32 + 4 * ty + (i - 4));
        const float bo = (t == 0) ? bias[ii] : 0.f;
        #pragma unroll
        for (int h = 0; h < 2; ++h) {
            const int c = h * 128 + 4 * tx;
            const int n = nbase + c;
            if (n < KL) {
                const float2 p0 = unpack2(acc[i][2 * h + 0]);
                const float2 p1 = unpack2(acc[i][2 * h + 1]);
                float4 r = make_float4(p0.x + bo, p0.y + bo, p1.x + bo, p1.y + bo);
                *(float4*)&Ub[(size_t)ii * KL + n] = r;
            }
        }
    }
}

// ---------------------------------------------------------------------------
// Kernel C: diffusion, accumulate into out (holds W0*x + bias).
// ---------------------------------------------------------------------------
__global__ __launch_bounds__(256, 2)
void diffuse_kernel(const float* __restrict__ a0, const float* __restrict__ a1,
                    float* __restrict__ out) {
    const int b = blockIdx.z;
    const int o0 = blockIdx.x * 4;
    const int j0 = blockIdx.y * 64;
    const int tid = threadIdx.x;
    const int tx = tid & 31, ty = tid >> 5;

    __shared__ __align__(16) float At[32][68];   // [kk][jj]
    __shared__ __align__(16) float Us[32][260];  // [kk][c]

    unsigned long long acc[8][4];
    #pragma unroll
    for (int i = 0; i < 8; ++i)
        #pragma unroll
        for (int p = 0; p < 4; ++p) acc[i][p] = 0ull;

    const float4 z4 = make_float4(0.f, 0.f, 0.f, 0.f);

    for (int t = 1; t <= 4; ++t) {
        const float* Amat;
        if      (t == 1) Amat = a0 + (size_t)b * KSQ;
        else if (t == 2) Amat = g_Asq + (size_t)(0 * B_DIM + b) * KSQ;
        else if (t == 3) Amat = a1 + (size_t)b * KSQ;
        else             Amat = g_Asq + (size_t)(1 * B_DIM + b) * KSQ;
        const float* Ut = g_U + (((size_t)b * 4 + (t - 1)) * C_DIM + o0) * KL;

        for (int k0 = 0; k0 < K_DIM; k0 += 32) {
            #pragma unroll
            for (int it = 0; it < 8; ++it) {     // A tile (transposed store)
                int e = tid + it * 256;
                int jj = e >> 5, kk = e & 31;
                int j = j0 + jj, k = k0 + kk;
                At[kk][jj] = (j < K_DIM && k < K_DIM) ? Amat[(size_t)j * K_DIM + k] : 0.f;
            }
            #pragma unroll
            for (int it = 0; it < 8; ++it) {     // U tile, float4
                int e = tid + it * 256;
                int kk = e >> 6, c = (e & 63) * 4;
                int k = k0 + kk;
                int o_loc = c >> 6, l = c & 63;
                float4 v = (k < K_DIM)
                    ? *(const float4*)&Ut[(size_t)o_loc * KL + (size_t)k * L_DIM + l] : z4;
                *(float4*)&Us[kk][c] = v;
            }
            __syncthreads();

            #pragma unroll 4
            for (int kk = 0; kk < 32; ++kk) {
                const float4 a0v = *(const float4*)&At[kk][4 * ty];
                const float4 a1v = *(const float4*)&At[kk][32 + 4 * ty];
                const ulonglong2 ua = *(const ulonglong2*)&Us[kk][4 * tx];
                const ulonglong2 ub = *(const ulonglong2*)&Us[kk][128 + 4 * tx];
                const float af[8] = {a0v.x, a0v.y, a0v.z, a0v.w, a1v.x, a1v.y, a1v.z, a1v.w};
                #pragma unroll
                for (int i = 0; i < 8; ++i) {
                    const unsigned long long a2 = pack2(af[i]);
                    acc[i][0] = ffma2(a2, ua.x, acc[i][0]);
                    acc[i][1] = ffma2(a2, ua.y, acc[i][1]);
                    acc[i][2] = ffma2(a2, ub.x, acc[i][2]);
                    acc[i][3] = ffma2(a2, ub.y, acc[i][3]);
                }
            }
            __syncthreads();
        }
    }

    float* Ob = out + ((size_t)b * C_DIM + o0) * KL;
    #pragma unroll
    for (int i = 0; i < 8; ++i) {
        const int jj = (i < 4) ? (4 * ty + i) : (32 + 4 * ty + (i - 4));
        const int j = j0 + jj;
        if (j < K_DIM) {
            #pragma unroll
            for (int h = 0; h < 2; ++h) {
                const int c = h * 128 + 4 * tx;
                const int o_loc = c >> 6, l = c & 63;
                const float2 p0 = unpack2(acc[i][2 * h + 0]);
                const float2 p1 = unpack2(acc[i][2 * h + 1]);
                const size_t off = (size_t)o_loc * KL + (size_t)j * L_DIM + l;
                const float4 u0 = *(const float4*)&Ob[off];
                float4 r = make_float4(p0.x + u0.x, p0.y + u0.y,
                                       p1.x + u0.z, p1.y + u0.w);
                *(float4*)&Ob[off] = r;
            }
        }
    }
}

extern "C" void kernel_launch(void* const* d_in, const int* in_sizes, int n_in,
                              void* d_out, int out_size) {
    (void)in_sizes; (void)n_in; (void)out_size;
    const float* x    = (const float*)d_in[0];
    const float* a0   = (const float*)d_in[1];
    const float* a1   = (const float*)d_in[2];
    const float* W    = (const float*)d_in[3];
    const float* bias = (const float*)d_in[4];
    float* out        = (float*)d_out;

    {
        dim3 grid((K_DIM + 31) / 32, (K_DIM + 31) / 32, 2 * B_DIM);
        dim3 block(16, 16);
        square_kernel<<<grid, block>>>(a0, a1);
    }
    {
        dim3 grid((KL + 255) / 256, 5, B_DIM);
        chanmix_kernel<<<grid, 256>>>(x, W, bias, out);
    }
    {
        dim3 grid(C_DIM / 4, (K_DIM + 63) / 64, B_DIM);
        diffuse_kernel<<<grid, 256>>>(a0, a1, out);
    }
}

// round 7
// speedup vs baseline: 1.0996x; 1.0125x over previous
#include <cuda_runtime.h>
#include <cuda_bf16.h>
#include <cstdint>

#define B_DIM 16
#define C_DIM 64
#define K_DIM 207
#define L_DIM 64
#define KL    13248
#define C_IN  320
#define KSQ   (K_DIM * K_DIM)

// scratch
__device__ float g_Asq[2 * B_DIM * KSQ];
__device__ __nv_bfloat16 g_Mh[(size_t)B_DIM * 4 * 256 * 256];   // padded split M_t
__device__ __nv_bfloat16 g_Ml[(size_t)B_DIM * 4 * 256 * 256];
__device__ __nv_bfloat16 g_Uh[(size_t)B_DIM * 4 * C_DIM * K_DIM * L_DIM];  // [b][t][o][k][l]
__device__ __nv_bfloat16 g_Ul[(size_t)B_DIM * 4 * C_DIM * K_DIM * L_DIM];

__device__ __forceinline__ uint32_t smem_u32(const void* p) {
    uint32_t a;
    asm("{ .reg .u64 t; cvta.to.shared.u64 t, %1; cvt.u32.u64 %0, t; }" : "=r"(a) : "l"(p));
    return a;
}
__device__ __forceinline__ void split2(float v, __nv_bfloat16& h, __nv_bfloat16& l) {
    h = __float2bfloat16(v);
    l = __float2bfloat16(v - __bfloat162float(h));
}
__device__ __forceinline__ void ldsm4(uint32_t* r, uint32_t addr) {
    asm volatile("ldmatrix.sync.aligned.m8n8.x4.shared.b16 {%0,%1,%2,%3}, [%4];"
                 : "=r"(r[0]), "=r"(r[1]), "=r"(r[2]), "=r"(r[3]) : "r"(addr));
}
__device__ __forceinline__ void mma16816(float* d, const uint32_t* a, const uint32_t* b) {
    asm volatile(
        "mma.sync.aligned.m16n8k16.row.col.f32.bf16.bf16.f32 "
        "{%0,%1,%2,%3}, {%4,%5,%6,%7}, {%8,%9}, {%0,%1,%2,%3};"
        : "+f"(d[0]), "+f"(d[1]), "+f"(d[2]), "+f"(d[3])
        : "r"(a[0]), "r"(a[1]), "r"(a[2]), "r"(a[3]), "r"(b[0]), "r"(b[1]));
}

// ---------------------------------------------------------------- A^2 (proven)
__global__ __launch_bounds__(256)
void square_kernel(const float* __restrict__ a0, const float* __restrict__ a1) {
    const int z = blockIdx.z;
    const int which = z & 1, b = z >> 1;
    const float* A = (which == 0 ? a0 : a1) + (size_t)b * KSQ;
    float* O = g_Asq + (size_t)(which * B_DIM + b) * KSQ;
    const int tx = threadIdx.x, ty = threadIdx.y;
    const int tid = ty * 16 + tx;
    const int j0 = blockIdx.y * 32, k0 = blockIdx.x * 32;
    __shared__ float As[32][33];
    __shared__ float Bs[32][33];
    float acc[2][2] = {{0.f, 0.f}, {0.f, 0.f}};
    for (int m0 = 0; m0 < K_DIM; m0 += 32) {
        #pragma unroll
        for (int q = 0; q < 4; ++q) {
            int e = tid + q * 256;
            int r = e >> 5, cc = e & 31;
            int jA = j0 + r, mA = m0 + cc;
            As[r][cc] = (jA < K_DIM && mA < K_DIM) ? A[(size_t)jA * K_DIM + mA] : 0.f;
            int mB = m0 + r, kB = k0 + cc;
            Bs[r][cc] = (mB < K_DIM && kB < K_DIM) ? A[(size_t)mB * K_DIM + kB] : 0.f;
        }
        __syncthreads();
        #pragma unroll 8
        for (int mm = 0; mm < 32; ++mm) {
            float av0 = As[ty][mm], av1 = As[ty + 16][mm];
            float bv0 = Bs[mm][tx], bv1 = Bs[mm][tx + 16];
            acc[0][0] += av0 * bv0; acc[0][1] += av0 * bv1;
            acc[1][0] += av1 * bv0; acc[1][1] += av1 * bv1;
        }
        __syncthreads();
    }
    #pragma unroll
    for (int qi = 0; qi < 2; ++qi)
        #pragma unroll
        for (int qj = 0; qj < 2; ++qj) {
            int j = j0 + ty + qi * 16, k = k0 + tx + qj * 16;
            if (j < K_DIM && k < K_DIM) O[(size_t)j * K_DIM + k] = acc[qi][qj];
        }
}

// ---------------------------------------------------------------- split M_t, padded 256x256
// t: 0->a0, 1->a0^2, 2->a1, 3->a1^2
__global__ __launch_bounds__(256)
void splitM_kernel(const float* __restrict__ a0, const float* __restrict__ a1) {
    size_t e = (size_t)blockIdx.x * 256 + threadIdx.x;
    int k = (int)(e & 255), j = (int)((e >> 8) & 255);
    int t = (int)((e >> 16) & 3), b = (int)(e >> 18);
    float v = 0.f;
    if (j < K_DIM && k < K_DIM) {
        const float* M;
        if (t == 0)      M = a0 + (size_t)b * KSQ;
        else if (t == 1) M = g_Asq + (size_t)b * KSQ;
        else if (t == 2) M = a1 + (size_t)b * KSQ;
        else             M = g_Asq + (size_t)(B_DIM + b) * KSQ;
        v = M[(size_t)j * K_DIM + k];
    }
    __nv_bfloat16 h, l; split2(v, h, l);
    g_Mh[e] = h; g_Ml[e] = l;
}

// ---------------------------------------------------------------- Stage B
// Block (kcol, b): D[m=(t,o)][n=l] = sum_c W[m][c] * x[b][c][kcol*64+l]
// smem rows stride 72 bf16 (144B -> conflict-free ldmatrix)
#define BW_H 0
#define BW_L 46080
#define BX_H 92160
#define BX_L 101376
#define B_SMEM 110592

__global__ __launch_bounds__(320)
void chanmix_mma(const float* __restrict__ x, const float* __restrict__ W,
                 const float* __restrict__ bias, float* __restrict__ out) {
    extern __shared__ __align__(16) char smem[];
    const int tid = threadIdx.x, lane = tid & 31, wid = tid >> 5;
    const int b = blockIdx.y, kcol = blockIdx.x;

    // stage W (320 x 64) hi/lo
    #pragma unroll 4
    for (int it = 0; it < 64; ++it) {
        int e = tid + it * 320;
        int m = e >> 6, c = e & 63;
        int t = m >> 6, o = m & 63;
        float v = W[(size_t)o * C_IN + t * 64 + c];
        __nv_bfloat16 h, l; split2(v, h, l);
        int off = (m * 72 + c) * 2;
        *(__nv_bfloat16*)(smem + BW_H + off) = h;
        *(__nv_bfloat16*)(smem + BW_L + off) = l;
    }
    // stage x tile as [l][c]
    const float* xs = x + (size_t)b * C_DIM * KL + kcol * 64;
    #pragma unroll
    for (int it = 0; it < 13; ++it) {
        int e = tid + it * 320;
        if (e < 4096) {
            int c = e >> 6, l = e & 63;
            float v = xs[(size_t)c * KL + l];
            __nv_bfloat16 h, lo; split2(v, h, lo);
            int off = (l * 72 + c) * 2;
            *(__nv_bfloat16*)(smem + BX_H + off) = h;
            *(__nv_bfloat16*)(smem + BX_L + off) = lo;
        }
    }
    __syncthreads();

    float acc[2][8][4];
    #pragma unroll
    for (int i = 0; i < 2; ++i)
        #pragma unroll
        for (int j = 0; j < 8; ++j)
            #pragma unroll
            for (int q = 0; q < 4; ++q) acc[i][j][q] = 0.f;

    const uint32_t sb = smem_u32(smem);
    const int rowA = lane & 15, colA = (lane >> 4) * 8;
    const int rowB = (lane & 7) + ((lane >> 4) << 3), colB = ((lane >> 3) & 1) * 8;

    #pragma unroll
    for (int c0 = 0; c0 < 64; c0 += 16) {
        uint32_t ah[2][4], al[2][4];
        #pragma unroll
        for (int mt = 0; mt < 2; ++mt) {
            uint32_t ra = sb + BW_H + (uint32_t)(((wid * 32 + mt * 16 + rowA) * 72 + c0 + colA) * 2);
            ldsm4(ah[mt], ra);
            ldsm4(al[mt], ra + (BW_L - BW_H));
        }
        #pragma unroll
        for (int p = 0; p < 4; ++p) {
            uint32_t bh[4], bl[4];
            uint32_t rb = sb + BX_H + (uint32_t)(((p * 16 + rowB) * 72 + c0 + colB) * 2);
            ldsm4(bh, rb);
            ldsm4(bl, rb + (BX_L - BX_H));
            #pragma unroll
            for (int mt = 0; mt < 2; ++mt)
                #pragma unroll
                for (int jj = 0; jj < 2; ++jj) {
                    float* d = acc[mt][p * 2 + jj];
                    mma16816(d, ah[mt], &bh[jj * 2]);
                    mma16816(d, ah[mt], &bl[jj * 2]);
                    mma16816(d, al[mt], &bh[jj * 2]);
                }
        }
    }

    // epilogue
    #pragma unroll
    for (int mt = 0; mt < 2; ++mt) {
        #pragma unroll
        for (int rsel = 0; rsel < 2; ++rsel) {
            const int m = wid * 32 + mt * 16 + (lane >> 2) + rsel * 8;
            const int t = m >> 6, o = m & 63;
            if (t == 0) {
                const float bo = bias[o];
                float* op = out + ((size_t)b * 64 + o) * KL + (size_t)kcol * 64;
                #pragma unroll
                for (int j = 0; j < 8; ++j) {
                    int l = j * 8 + (lane & 3) * 2;
                    float2 v = make_float2(acc[mt][j][rsel * 2] + bo,
                                           acc[mt][j][rsel * 2 + 1] + bo);
                    *(float2*)(op + l) = v;
                }
            } else {
                const size_t rb = ((((size_t)b * 4 + (t - 1)) * 64 + o) * K_DIM + kcol) * 64;
                uint32_t* Uhp = (uint32_t*)(g_Uh + rb);
                uint32_t* Ulp = (uint32_t*)(g_Ul + rb);
                #pragma unroll
                for (int j = 0; j < 8; ++j) {
                    int l = j * 8 + (lane & 3) * 2;
                    float v0 = acc[mt][j][rsel * 2], v1 = acc[mt][j][rsel * 2 + 1];
                    __nv_bfloat16 h0, l0, h1, l1;
                    split2(v0, h0, l0); split2(v1, h1, l1);
                    Uhp[l >> 1] = (uint32_t)__bfloat16_as_ushort(h0) |
                                  ((uint32_t)__bfloat16_as_ushort(h1) << 16);
                    Ulp[l >> 1] = (uint32_t)__bfloat16_as_ushort(l0) |
                                  ((uint32_t)__bfloat16_as_ushort(l1) << 16);
                }
            }
        }
    }
}

// ---------------------------------------------------------------- Stage C
// Block (o, b): out[b,o,j,l] += sum_t sum_k M_t[j,k] * U[b,t,o,k,l]
#define CA_H 0
#define CA_L 36864
#define CB_H 73728
#define CB_L 82944
#define C_SMEM 92160

__global__ __launch_bounds__(256)
void diffuse_mma(float* __restrict__ out) {
    extern __shared__ __align__(16) char smem[];
    const int tid = threadIdx.x, lane = tid & 31, wid = tid >> 5;
    const int b = blockIdx.y, o = blockIdx.x;

    float acc[2][8][4];
    #pragma unroll
    for (int i = 0; i < 2; ++i)
        #pragma unroll
        for (int j = 0; j < 8; ++j)
            #pragma unroll
            for (int q = 0; q < 4; ++q) acc[i][j][q] = 0.f;

    const uint32_t sb = smem_u32(smem);
    const int rowA = lane & 15, colA = (lane >> 4) * 8;
    const int rowB = (lane & 7) + ((lane >> 4) << 3), colB = ((lane >> 3) & 1) * 8;

    for (int t = 0; t < 4; ++t) {
        const uint2* Mh2 = (const uint2*)(g_Mh + ((size_t)(b * 4 + t) << 16));
        const uint2* Ml2 = (const uint2*)(g_Ml + ((size_t)(b * 4 + t) << 16));
        const uint32_t* Uh32 = (const uint32_t*)g_Uh + (((size_t)b * 4 + t) * 64 + o) * K_DIM * 32;
        const uint32_t* Ul32 = (const uint32_t*)g_Ul + (((size_t)b * 4 + t) * 64 + o) * K_DIM * 32;

        for (int kc = 0; kc < 4; ++kc) {
            // stage A: 256 j x 64 k (uint2 = 4 bf16)
            #pragma unroll
            for (int it = 0; it < 16; ++it) {
                int e = tid + it * 256;
                int j = e >> 4, u = e & 15;   // u indexes uint2 within the 64-col chunk
                uint2 vh = Mh2[(size_t)j * 64 + kc * 16 + u];
                uint2 vl = Ml2[(size_t)j * 64 + kc * 16 + u];
                int off = (j * 72 + u * 4) * 2;
                *(uint2*)(smem + CA_H + off) = vh;
                *(uint2*)(smem + CA_L + off) = vl;
            }
            // stage B: transpose U[k][l] -> Bs[l][k], guard k < 207
            #pragma unroll
            for (int it = 0; it < 8; ++it) {
                int e = tid + it * 256;
                int kk = e >> 5, lp = e & 31;
                int kg = kc * 64 + kk;
                uint32_t vh = 0, vl = 0;
                if (kg < K_DIM) { vh = Uh32[(size_t)kg * 32 + lp]; vl = Ul32[(size_t)kg * 32 + lp]; }
                int l0 = lp * 2;
                *(__nv_bfloat16*)(smem + CB_H + ((l0) * 72 + kk) * 2) =
                    __ushort_as_bfloat16((unsigned short)(vh & 0xFFFF));
                *(__nv_bfloat16*)(smem + CB_H + ((l0 + 1) * 72 + kk) * 2) =
                    __ushort_as_bfloat16((unsigned short)(vh >> 16));
                *(__nv_bfloat16*)(smem + CB_L + ((l0) * 72 + kk) * 2) =
                    __ushort_as_bfloat16((unsigned short)(vl & 0xFFFF));
                *(__nv_bfloat16*)(smem + CB_L + ((l0 + 1) * 72 + kk) * 2) =
                    __ushort_as_bfloat16((unsigned short)(vl >> 16));
            }
            __syncthreads();

            #pragma unroll
            for (int c0 = 0; c0 < 64; c0 += 16) {
                uint32_t ah[2][4], al[2][4];
                #pragma unroll
                for (int mt = 0; mt < 2; ++mt) {
                    uint32_t ra = sb + CA_H + (uint32_t)(((wid * 32 + mt * 16 + rowA) * 72 + c0 + colA) * 2);
                    ldsm4(ah[mt], ra);
                    ldsm4(al[mt], ra + (CA_L - CA_H));
                }
                #pragma unroll
                for (int p = 0; p < 4; ++p) {
                    uint32_t bh[4], bl[4];
                    uint32_t rbb = sb + CB_H + (uint32_t)(((p * 16 + rowB) * 72 + c0 + colB) * 2);
                    ldsm4(bh, rbb);
                    ldsm4(bl, rbb + (CB_L - CB_H));
                    #pragma unroll
                    for (int mt = 0; mt < 2; ++mt)
                        #pragma unroll
                        for (int jj = 0; jj < 2; ++jj) {
                            float* d = acc[mt][p * 2 + jj];
                            mma16816(d, ah[mt], &bh[jj * 2]);
                            mma16816(d, ah[mt], &bl[jj * 2]);
                            mma16816(d, al[mt], &bh[jj * 2]);
                        }
                }
            }
            __syncthreads();
        }
    }

    // epilogue: RMW onto out
    float* ob = out + ((size_t)b * 64 + o) * KL;
    #pragma unroll
    for (int mt = 0; mt < 2; ++mt) {
        #pragma unroll
        for (int rsel = 0; rsel < 2; ++rsel) {
            const int j = wid * 32 + mt * 16 + (lane >> 2) + rsel * 8;
            if (j < K_DIM) {
                float* op = ob + (size_t)j * 64;
                #pragma unroll
                for (int n8 = 0; n8 < 8; ++n8) {
                    int l = n8 * 8 + (lane & 3) * 2;
                    float2 u = *(float2*)(op + l);
                    u.x += acc[mt][n8][rsel * 2];
                    u.y += acc[mt][n8][rsel * 2 + 1];
                    *(float2*)(op + l) = u;
                }
            }
        }
    }
}

// ----------------------------------------------------------------
extern "C" void kernel_launch(void* const* d_in, const int* in_sizes, int n_in,
                              void* d_out, int out_size) {
    (void)in_sizes; (void)n_in; (void)out_size;
    const float* x    = (const float*)d_in[0];
    const float* a0   = (const float*)d_in[1];
    const float* a1   = (const float*)d_in[2];
    const float* W    = (const float*)d_in[3];
    const float* bias = (const float*)d_in[4];
    float* out        = (float*)d_out;

    cudaFuncSetAttribute(chanmix_mma, cudaFuncAttributeMaxDynamicSharedMemorySize, B_SMEM);
    cudaFuncSetAttribute(diffuse_mma, cudaFuncAttributeMaxDynamicSharedMemorySize, C_SMEM);

    {
        dim3 grid((K_DIM + 31) / 32, (K_DIM + 31) / 32, 2 * B_DIM);
        dim3 block(16, 16);
        square_kernel<<<grid, block>>>(a0, a1);
    }
    splitM_kernel<<<16384, 256>>>(a0, a1);
    {
        dim3 grid(K_DIM, B_DIM);   // 207 x 16
        chanmix_mma<<<grid, 320, B_SMEM>>>(x, W, bias, out);
    }
    {
        dim3 grid(C_DIM, B_DIM);   // 64 x 16
        diffuse_mma<<<grid, 256, C_SMEM>>>(out);
    }
}

// round 9
// speedup vs baseline: 1.6910x; 1.5378x over previous
#include <cuda_runtime.h>
#include <cuda_bf16.h>
#include <cstdint>

#define B_DIM 16
#define C_DIM 64
#define K_DIM 207
#define L_DIM 64
#define KL    13248
#define C_IN  320
#define KSQ   (K_DIM * K_DIM)

// scratch
__device__ float g_Asq[2 * B_DIM * KSQ];
__device__ __nv_bfloat16 g_Mh[(size_t)B_DIM * 4 * 256 * 256];   // padded split M_t
__device__ __nv_bfloat16 g_Ml[(size_t)B_DIM * 4 * 256 * 256];
__device__ __nv_bfloat16 g_Wh[320 * 64];                        // split W
__device__ __nv_bfloat16 g_Wl[320 * 64];
__device__ __nv_bfloat16 g_Uh[(size_t)B_DIM * 4 * C_DIM * K_DIM * L_DIM];  // [b][t][o][k][l]
__device__ __nv_bfloat16 g_Ul[(size_t)B_DIM * 4 * C_DIM * K_DIM * L_DIM];

__device__ __forceinline__ uint32_t smem_u32(const void* p) {
    uint32_t a;
    asm("{ .reg .u64 t; cvta.to.shared.u64 t, %1; cvt.u32.u64 %0, t; }" : "=r"(a) : "l"(p));
    return a;
}
__device__ __forceinline__ void split2(float v, __nv_bfloat16& h, __nv_bfloat16& l) {
    h = __float2bfloat16(v);
    l = __float2bfloat16(v - __bfloat162float(h));
}
__device__ __forceinline__ void ldsm4(uint32_t* r, uint32_t addr) {
    asm volatile("ldmatrix.sync.aligned.m8n8.x4.shared.b16 {%0,%1,%2,%3}, [%4];"
                 : "=r"(r[0]), "=r"(r[1]), "=r"(r[2]), "=r"(r[3]) : "r"(addr));
}
__device__ __forceinline__ void ldsm4t(uint32_t* r, uint32_t addr) {
    asm volatile("ldmatrix.sync.aligned.m8n8.x4.trans.shared.b16 {%0,%1,%2,%3}, [%4];"
                 : "=r"(r[0]), "=r"(r[1]), "=r"(r[2]), "=r"(r[3]) : "r"(addr));
}
__device__ __forceinline__ void mma16816(float* d, const uint32_t* a, const uint32_t* b) {
    asm volatile(
        "mma.sync.aligned.m16n8k16.row.col.f32.bf16.bf16.f32 "
        "{%0,%1,%2,%3}, {%4,%5,%6,%7}, {%8,%9}, {%0,%1,%2,%3};"
        : "+f"(d[0]), "+f"(d[1]), "+f"(d[2]), "+f"(d[3])
        : "r"(a[0]), "r"(a[1]), "r"(a[2]), "r"(a[3]), "r"(b[0]), "r"(b[1]));
}
__device__ __forceinline__ void cpa16(uint32_t dst, const void* src) {
    asm volatile("cp.async.cg.shared.global [%0], [%1], 16;" :: "r"(dst), "l"(src));
}
__device__ __forceinline__ void cpa16z(uint32_t dst, const void* src, int sz) {
    asm volatile("cp.async.cg.shared.global [%0], [%1], 16, %2;" :: "r"(dst), "l"(src), "r"(sz));
}
#define CP_COMMIT() asm volatile("cp.async.commit_group;" ::: "memory")
#define CP_WAIT0()  asm volatile("cp.async.wait_group 0;" ::: "memory")
#define CP_WAIT1()  asm volatile("cp.async.wait_group 1;" ::: "memory")

// ---------------------------------------------------------------- A^2 (proven)
__global__ __launch_bounds__(256)
void square_kernel(const float* __restrict__ a0, const float* __restrict__ a1) {
    const int z = blockIdx.z;
    const int which = z & 1, b = z >> 1;
    const float* A = (which == 0 ? a0 : a1) + (size_t)b * KSQ;
    float* O = g_Asq + (size_t)(which * B_DIM + b) * KSQ;
    const int tx = threadIdx.x, ty = threadIdx.y;
    const int tid = ty * 16 + tx;
    const int j0 = blockIdx.y * 32, k0 = blockIdx.x * 32;
    __shared__ float As[32][33];
    __shared__ float Bs[32][33];
    float acc[2][2] = {{0.f, 0.f}, {0.f, 0.f}};
    for (int m0 = 0; m0 < K_DIM; m0 += 32) {
        #pragma unroll
        for (int q = 0; q < 4; ++q) {
            int e = tid + q * 256;
            int r = e >> 5, cc = e & 31;
            int jA = j0 + r, mA = m0 + cc;
            As[r][cc] = (jA < K_DIM && mA < K_DIM) ? A[(size_t)jA * K_DIM + mA] : 0.f;
            int mB = m0 + r, kB = k0 + cc;
            Bs[r][cc] = (mB < K_DIM && kB < K_DIM) ? A[(size_t)mB * K_DIM + kB] : 0.f;
        }
        __syncthreads();
        #pragma unroll 8
        for (int mm = 0; mm < 32; ++mm) {
            float av0 = As[ty][mm], av1 = As[ty + 16][mm];
            float bv0 = Bs[mm][tx], bv1 = Bs[mm][tx + 16];
            acc[0][0] += av0 * bv0; acc[0][1] += av0 * bv1;
            acc[1][0] += av1 * bv0; acc[1][1] += av1 * bv1;
        }
        __syncthreads();
    }
    #pragma unroll
    for (int qi = 0; qi < 2; ++qi)
        #pragma unroll
        for (int qj = 0; qj < 2; ++qj) {
            int j = j0 + ty + qi * 16, k = k0 + tx + qj * 16;
            if (j < K_DIM && k < K_DIM) O[(size_t)j * K_DIM + k] = acc[qi][qj];
        }
}

// ---------------------------------------------------------------- split M_t padded, split W
__global__ __launch_bounds__(256)
void splitM_kernel(const float* __restrict__ a0, const float* __restrict__ a1) {
    size_t e = (size_t)blockIdx.x * 256 + threadIdx.x;
    int k = (int)(e & 255), j = (int)((e >> 8) & 255);
    int t = (int)((e >> 16) & 3), b = (int)(e >> 18);
    float v = 0.f;
    if (j < K_DIM && k < K_DIM) {
        const float* M;
        if (t == 0)      M = a0 + (size_t)b * KSQ;
        else if (t == 1) M = g_Asq + (size_t)b * KSQ;
        else if (t == 2) M = a1 + (size_t)b * KSQ;
        else             M = g_Asq + (size_t)(B_DIM + b) * KSQ;
        v = M[(size_t)j * K_DIM + k];
    }
    __nv_bfloat16 h, l; split2(v, h, l);
    g_Mh[e] = h; g_Ml[e] = l;
}

__global__ __launch_bounds__(256)
void splitW_kernel(const float* __restrict__ W) {
    int e = blockIdx.x * 256 + threadIdx.x;
    if (e < 320 * 64) {
        int m = e >> 6, c = e & 63;
        int t = m >> 6, o = m & 63;
        float v = W[(size_t)o * C_IN + t * 64 + c];
        __nv_bfloat16 h, l; split2(v, h, l);
        g_Wh[e] = h; g_Wl[e] = l;
    }
}

// ---------------------------------------------------------------- Stage B
// Block (kcol, b): D[m=(t,o)][n=l] = sum_c W[m][c] * x[b][c][kcol*64+l]
// 640 thr = 20 warps, warp w owns m rows [w*16, w*16+16). B via ldmatrix.trans.
#define BW_H 0
#define BW_L 46080
#define BX_H 92160
#define BX_L 101376
#define B_SMEM 110592

__global__ __launch_bounds__(640)
void chanmix_mma(const float* __restrict__ x, const float* __restrict__ bias,
                 float* __restrict__ out) {
    extern __shared__ __align__(16) char smem[];
    const int tid = threadIdx.x, lane = tid & 31, w = tid >> 5;
    const int b = blockIdx.y, kcol = blockIdx.x;
    const uint32_t sb = smem_u32(smem);

    // stage W via cp.async (rows m, 128B contiguous in g_Wh)
    #pragma unroll
    for (int it = 0; it < 4; ++it) {
        int e = tid + it * 640;
        if (e < 2560) {
            int r = e >> 3, u = e & 7;
            cpa16(sb + BW_H + r * 144 + u * 16, (const char*)g_Wh + r * 128 + u * 16);
            cpa16(sb + BW_L + r * 144 + u * 16, (const char*)g_Wl + r * 128 + u * 16);
        }
    }
    CP_COMMIT();
    // stage x tile [c][l] rows c (k-major for trans-B)
    const float* xs = x + (size_t)b * C_DIM * KL + (size_t)kcol * 64;
    #pragma unroll
    for (int it = 0; it < 7; ++it) {
        int e = tid + it * 640;
        if (e < 4096) {
            int c = e >> 6, l = e & 63;
            float v = xs[(size_t)c * KL + l];
            __nv_bfloat16 h, lo; split2(v, h, lo);
            *(__nv_bfloat16*)(smem + BX_H + (c * 72 + l) * 2) = h;
            *(__nv_bfloat16*)(smem + BX_L + (c * 72 + l) * 2) = lo;
        }
    }
    CP_WAIT0();
    __syncthreads();

    float acc[8][4];
    #pragma unroll
    for (int j = 0; j < 8; ++j)
        #pragma unroll
        for (int q = 0; q < 4; ++q) acc[j][q] = 0.f;

    const int rowA = lane & 15, colA = (lane >> 4) * 8;
    const int rowB = lane & 15, colB = (lane >> 4) * 8;

    #pragma unroll
    for (int c0 = 0; c0 < 64; c0 += 16) {
        uint32_t ah[4], al[4];
        uint32_t ra = sb + BW_H + (uint32_t)(((w * 16 + rowA) * 72 + c0 + colA) * 2);
        ldsm4(ah, ra);
        ldsm4(al, ra + (BW_L - BW_H));
        #pragma unroll
        for (int p = 0; p < 4; ++p) {
            uint32_t bh[4], bl[4];
            uint32_t rb = sb + BX_H + (uint32_t)(((c0 + rowB) * 72 + p * 16 + colB) * 2);
            ldsm4t(bh, rb);
            ldsm4t(bl, rb + (BX_L - BX_H));
            #pragma unroll
            for (int jj = 0; jj < 2; ++jj) {
                float* d = acc[p * 2 + jj];
                mma16816(d, ah, &bh[jj * 2]);
                mma16816(d, ah, &bl[jj * 2]);
                mma16816(d, al, &bh[jj * 2]);
            }
        }
    }

    // epilogue
    #pragma unroll
    for (int rsel = 0; rsel < 2; ++rsel) {
        const int m = w * 16 + (lane >> 2) + rsel * 8;
        const int t = m >> 6, o = m & 63;
        if (t == 0) {
            const float bo = bias[o];
            float* op = out + ((size_t)b * 64 + o) * KL + (size_t)kcol * 64;
            #pragma unroll
            for (int n8 = 0; n8 < 8; ++n8) {
                int l = n8 * 8 + (lane & 3) * 2;
                *(float2*)(op + l) = make_float2(acc[n8][rsel * 2] + bo,
                                                 acc[n8][rsel * 2 + 1] + bo);
            }
        } else {
            const size_t rb = ((((size_t)b * 4 + (t - 1)) * 64 + o) * K_DIM + kcol) * 64;
            uint32_t* Uhp = (uint32_t*)(g_Uh + rb);
            uint32_t* Ulp = (uint32_t*)(g_Ul + rb);
            #pragma unroll
            for (int n8 = 0; n8 < 8; ++n8) {
                int l = n8 * 8 + (lane & 3) * 2;
                __nv_bfloat16 h0, l0, h1, l1;
                split2(acc[n8][rsel * 2], h0, l0);
                split2(acc[n8][rsel * 2 + 1], h1, l1);
                Uhp[l >> 1] = (uint32_t)__bfloat16_as_ushort(h0) |
                              ((uint32_t)__bfloat16_as_ushort(h1) << 16);
                Ulp[l >> 1] = (uint32_t)__bfloat16_as_ushort(l0) |
                              ((uint32_t)__bfloat16_as_ushort(l1) << 16);
            }
        }
    }
}

// ---------------------------------------------------------------- Stage C
// Block (o, b): out[b,o,j,l] += sum_t sum_k M_t[j,k] * U[b,t,o,k,l]
// 512 thr = 16 warps (warp w owns j rows w*16..+16). cp.async double-buffered.
#define CBUF 92160            // per-buffer: AH 36864 | AL 36864 | BH 9216 | BL 9216
#define C_AH 0
#define C_AL 36864
#define C_BH 73728
#define C_BL 82944
#define C_SMEM (2 * CBUF)

__global__ __launch_bounds__(512)
void diffuse_mma(float* __restrict__ out) {
    extern __shared__ __align__(16) char smem[];
    const int tid = threadIdx.x, lane = tid & 31, w = tid >> 5;
    const int b = blockIdx.y, o = blockIdx.x;
    const uint32_t sb = smem_u32(smem);

    float acc[8][4];
    #pragma unroll
    for (int j = 0; j < 8; ++j)
        #pragma unroll
        for (int q = 0; q < 4; ++q) acc[j][q] = 0.f;

    const int rowA = lane & 15, colA = (lane >> 4) * 8;
    const int rowB = lane & 15, colB = (lane >> 4) * 8;

    auto stage = [&](int s, int buf) {
        const int t = s >> 2, kc = s & 3;
        const char* Mh = (const char*)(g_Mh + ((size_t)(b * 4 + t) << 16));
        const char* Ml = (const char*)(g_Ml + ((size_t)(b * 4 + t) << 16));
        const char* Uh = (const char*)g_Uh + ((((size_t)b * 4 + t) * 64 + o) * K_DIM) * 128;
        const char* Ul = (const char*)g_Ul + ((((size_t)b * 4 + t) * 64 + o) * K_DIM) * 128;
        const uint32_t base = sb + buf * CBUF;
        #pragma unroll
        for (int it = 0; it < 4; ++it) {      // A: 256 rows x 8 x 16B (hi+lo)
            int e = tid + it * 512;
            int r = e >> 3, u = e & 7;
            cpa16(base + C_AH + r * 144 + u * 16, Mh + r * 512 + kc * 128 + u * 16);
            cpa16(base + C_AL + r * 144 + u * 16, Ml + r * 512 + kc * 128 + u * 16);
        }
        {                                      // B: 64 k-rows x 8 x 16B, zfill pad
            int r = tid >> 3, u = tid & 7;
            int kg = kc * 64 + r;
            int sz = (kg < K_DIM) ? 16 : 0;
            size_t so = (size_t)((kg < K_DIM) ? kg : 0) * 128 + u * 16;
            cpa16z(base + C_BH + r * 144 + u * 16, Uh + so, sz);
            cpa16z(base + C_BL + r * 144 + u * 16, Ul + so, sz);
        }
        CP_COMMIT();
    };

    stage(0, 0);
    for (int s = 0; s < 16; ++s) {
        if (s + 1 < 16) { stage(s + 1, (s + 1) & 1); CP_WAIT1(); }
        else            { CP_WAIT0(); }
        __syncthreads();
        const uint32_t base = sb + (s & 1) * CBUF;
        #pragma unroll
        for (int c0 = 0; c0 < 64; c0 += 16) {
            uint32_t ah[4], al[4];
            uint32_t ra = base + C_AH + (uint32_t)(((w * 16 + rowA) * 72 + c0 + colA) * 2);
            ldsm4(ah, ra);
            ldsm4(al, ra + (C_AL - C_AH));
            #pragma unroll
            for (int p = 0; p < 4; ++p) {
                uint32_t bh[4], bl[4];
                uint32_t rb = base + C_BH + (uint32_t)(((c0 + rowB) * 72 + p * 16 + colB) * 2);
                ldsm4t(bh, rb);
                ldsm4t(bl, rb + (C_BL - C_BH));
                #pragma unroll
                for (int jj = 0; jj < 2; ++jj) {
                    float* d = acc[p * 2 + jj];
                    mma16816(d, ah, &bh[jj * 2]);
                    mma16816(d, ah, &bl[jj * 2]);
                    mma16816(d, al, &bh[jj * 2]);
                }
            }
        }
        __syncthreads();
    }

    // epilogue: RMW onto out
    float* ob = out + ((size_t)b * 64 + o) * KL;
    #pragma unroll
    for (int rsel = 0; rsel < 2; ++rsel) {
        const int j = w * 16 + (lane >> 2) + rsel * 8;
        if (j < K_DIM) {
            float* op = ob + (size_t)j * 64;
            #pragma unroll
            for (int n8 = 0; n8 < 8; ++n8) {
                int l = n8 * 8 + (lane & 3) * 2;
                float2 u = *(float2*)(op + l);
                u.x += acc[n8][rsel * 2];
                u.y += acc[n8][rsel * 2 + 1];
                *(float2*)(op + l) = u;
            }
        }
    }
}

// ----------------------------------------------------------------
extern "C" void kernel_launch(void* const* d_in, const int* in_sizes, int n_in,
                              void* d_out, int out_size) {
    (void)in_sizes; (void)n_in; (void)out_size;
    const float* x    = (const float*)d_in[0];
    const float* a0   = (const float*)d_in[1];
    const float* a1   = (const float*)d_in[2];
    const float* W    = (const float*)d_in[3];
    const float* bias = (const float*)d_in[4];
    float* out        = (float*)d_out;

    cudaFuncSetAttribute(chanmix_mma, cudaFuncAttributeMaxDynamicSharedMemorySize, B_SMEM);
    cudaFuncSetAttribute(diffuse_mma, cudaFuncAttributeMaxDynamicSharedMemorySize, C_SMEM);

    {
        dim3 grid((K_DIM + 31) / 32, (K_DIM + 31) / 32, 2 * B_DIM);
        dim3 block(16, 16);
        square_kernel<<<grid, block>>>(a0, a1);
    }
    splitM_kernel<<<16384, 256>>>(a0, a1);
    splitW_kernel<<<80, 256>>>(W);
    {
        dim3 grid(K_DIM, B_DIM);   // 207 x 16
        chanmix_mma<<<grid, 640, B_SMEM>>>(x, bias, out);
    }
    {
        dim3 grid(C_DIM, B_DIM);   // 64 x 16
        diffuse_mma<<<grid, 512, C_SMEM>>>(out);
    }
}

// round 10
// speedup vs baseline: 1.7934x; 1.0606x over previous
#include <cuda_runtime.h>
#include <cuda_bf16.h>
#include <cstdint>

#define B_DIM 16
#define C_DIM 64
#define K_DIM 207
#define L_DIM 64
#define KL    13248
#define C_IN  320
#define KSQ   (K_DIM * K_DIM)

// scratch
__device__ float g_Asq[2 * B_DIM * KSQ];
__device__ __nv_bfloat16 g_Mh[(size_t)B_DIM * 4 * 256 * 256];   // padded split M_t
__device__ __nv_bfloat16 g_Ml[(size_t)B_DIM * 4 * 256 * 256];
__device__ __nv_bfloat16 g_Wh[320 * 64];                        // split W
__device__ __nv_bfloat16 g_Wl[320 * 64];
__device__ __nv_bfloat16 g_Uh[(size_t)B_DIM * 4 * C_DIM * K_DIM * L_DIM];  // [b][t][o][k][l]
__device__ __nv_bfloat16 g_Ul[(size_t)B_DIM * 4 * C_DIM * K_DIM * L_DIM];

__device__ __forceinline__ uint32_t smem_u32(const void* p) {
    uint32_t a;
    asm("{ .reg .u64 t; cvta.to.shared.u64 t, %1; cvt.u32.u64 %0, t; }" : "=r"(a) : "l"(p));
    return a;
}
__device__ __forceinline__ void split2(float v, __nv_bfloat16& h, __nv_bfloat16& l) {
    h = __float2bfloat16(v);
    l = __float2bfloat16(v - __bfloat162float(h));
}
__device__ __forceinline__ void ldsm4(uint32_t* r, uint32_t addr) {
    asm volatile("ldmatrix.sync.aligned.m8n8.x4.shared.b16 {%0,%1,%2,%3}, [%4];"
                 : "=r"(r[0]), "=r"(r[1]), "=r"(r[2]), "=r"(r[3]) : "r"(addr));
}
__device__ __forceinline__ void ldsm4t(uint32_t* r, uint32_t addr) {
    asm volatile("ldmatrix.sync.aligned.m8n8.x4.trans.shared.b16 {%0,%1,%2,%3}, [%4];"
                 : "=r"(r[0]), "=r"(r[1]), "=r"(r[2]), "=r"(r[3]) : "r"(addr));
}
__device__ __forceinline__ void mma16816(float* d, const uint32_t* a, const uint32_t* b) {
    asm volatile(
        "mma.sync.aligned.m16n8k16.row.col.f32.bf16.bf16.f32 "
        "{%0,%1,%2,%3}, {%4,%5,%6,%7}, {%8,%9}, {%0,%1,%2,%3};"
        : "+f"(d[0]), "+f"(d[1]), "+f"(d[2]), "+f"(d[3])
        : "r"(a[0]), "r"(a[1]), "r"(a[2]), "r"(a[3]), "r"(b[0]), "r"(b[1]));
}
__device__ __forceinline__ void cpa16(uint32_t dst, const void* src) {
    asm volatile("cp.async.cg.shared.global [%0], [%1], 16;" :: "r"(dst), "l"(src));
}
__device__ __forceinline__ void cpa16z(uint32_t dst, const void* src, int sz) {
    asm volatile("cp.async.cg.shared.global [%0], [%1], 16, %2;" :: "r"(dst), "l"(src), "r"(sz));
}
#define CP_COMMIT() asm volatile("cp.async.commit_group;" ::: "memory")
#define CP_WAIT0()  asm volatile("cp.async.wait_group 0;" ::: "memory")
#define CP_WAIT1()  asm volatile("cp.async.wait_group 1;" ::: "memory")

// ---------------------------------------------------------------- A^2 (proven)
__global__ __launch_bounds__(256)
void square_kernel(const float* __restrict__ a0, const float* __restrict__ a1) {
    const int z = blockIdx.z;
    const int which = z & 1, b = z >> 1;
    const float* A = (which == 0 ? a0 : a1) + (size_t)b * KSQ;
    float* O = g_Asq + (size_t)(which * B_DIM + b) * KSQ;
    const int tx = threadIdx.x, ty = threadIdx.y;
    const int tid = ty * 16 + tx;
    const int j0 = blockIdx.y * 32, k0 = blockIdx.x * 32;
    __shared__ float As[32][33];
    __shared__ float Bs[32][33];
    float acc[2][2] = {{0.f, 0.f}, {0.f, 0.f}};
    for (int m0 = 0; m0 < K_DIM; m0 += 32) {
        #pragma unroll
        for (int q = 0; q < 4; ++q) {
            int e = tid + q * 256;
            int r = e >> 5, cc = e & 31;
            int jA = j0 + r, mA = m0 + cc;
            As[r][cc] = (jA < K_DIM && mA < K_DIM) ? A[(size_t)jA * K_DIM + mA] : 0.f;
            int mB = m0 + r, kB = k0 + cc;
            Bs[r][cc] = (mB < K_DIM && kB < K_DIM) ? A[(size_t)mB * K_DIM + kB] : 0.f;
        }
        __syncthreads();
        #pragma unroll 8
        for (int mm = 0; mm < 32; ++mm) {
            float av0 = As[ty][mm], av1 = As[ty + 16][mm];
            float bv0 = Bs[mm][tx], bv1 = Bs[mm][tx + 16];
            acc[0][0] += av0 * bv0; acc[0][1] += av0 * bv1;
            acc[1][0] += av1 * bv0; acc[1][1] += av1 * bv1;
        }
        __syncthreads();
    }
    #pragma unroll
    for (int qi = 0; qi < 2; ++qi)
        #pragma unroll
        for (int qj = 0; qj < 2; ++qj) {
            int j = j0 + ty + qi * 16, k = k0 + tx + qj * 16;
            if (j < K_DIM && k < K_DIM) O[(size_t)j * K_DIM + k] = acc[qi][qj];
        }
}

// ---------------------------------------------------------------- split M_t padded, split W
__global__ __launch_bounds__(256)
void splitM_kernel(const float* __restrict__ a0, const float* __restrict__ a1) {
    size_t e = (size_t)blockIdx.x * 256 + threadIdx.x;
    int k = (int)(e & 255), j = (int)((e >> 8) & 255);
    int t = (int)((e >> 16) & 3), b = (int)(e >> 18);
    float v = 0.f;
    if (j < K_DIM && k < K_DIM) {
        const float* M;
        if (t == 0)      M = a0 + (size_t)b * KSQ;
        else if (t == 1) M = g_Asq + (size_t)b * KSQ;
        else if (t == 2) M = a1 + (size_t)b * KSQ;
        else             M = g_Asq + (size_t)(B_DIM + b) * KSQ;
        v = M[(size_t)j * K_DIM + k];
    }
    __nv_bfloat16 h, l; split2(v, h, l);
    g_Mh[e] = h; g_Ml[e] = l;
}

__global__ __launch_bounds__(256)
void splitW_kernel(const float* __restrict__ W) {
    int e = blockIdx.x * 256 + threadIdx.x;
    if (e < 320 * 64) {
        int m = e >> 6, c = e & 63;
        int t = m >> 6, o = m & 63;
        float v = W[(size_t)o * C_IN + t * 64 + c];
        __nv_bfloat16 h, l; split2(v, h, l);
        g_Wh[e] = h; g_Wl[e] = l;
    }
}

// ---------------------------------------------------------------- Stage B
// Block (kgrp, b): 4 k-columns per block. W staged once; x cp.async fp32
// double-buffer -> convert -> bf16 double-buffer -> MMA.
#define BW_H 0
#define BW_L 46080
#define BXF(buf)  (92160 + (buf) * 16384)     // fp32 x tile, 2 bufs
#define BXB(buf)  (124928 + (buf) * 18432)    // bf16 x h|l, 2 bufs (h at +0, l at +9216)
#define B_SMEM 161792
#define KGRP 4

__global__ __launch_bounds__(640)
void chanmix_mma(const float* __restrict__ x, const float* __restrict__ bias,
                 float* __restrict__ out) {
    extern __shared__ __align__(16) char smem[];
    const int tid = threadIdx.x, lane = tid & 31, w = tid >> 5;
    const int b = blockIdx.y;
    const int kbase = blockIdx.x * KGRP;
    const int G = (kbase + KGRP <= K_DIM) ? KGRP : (K_DIM - kbase);
    const uint32_t sb = smem_u32(smem);
    const float* xb = x + (size_t)b * C_DIM * KL;

    // stage W via cp.async (group) — once per block
    #pragma unroll
    for (int it = 0; it < 4; ++it) {
        int e = tid + it * 640;
        if (e < 2560) {
            int r = e >> 3, u = e & 7;
            cpa16(sb + BW_H + r * 144 + u * 16, (const char*)g_Wh + r * 128 + u * 16);
            cpa16(sb + BW_L + r * 144 + u * 16, (const char*)g_Wl + r * 128 + u * 16);
        }
    }
    CP_COMMIT();

    // preload x tile 0 (fp32): 64 c-rows x 256B
    {
        int e = tid;  // 1024 xfers, 640 threads: 2 iters
        #pragma unroll
        for (int it = 0; it < 2; ++it, e += 640)
            if (e < 1024) {
                int c = e >> 4, u = e & 15;
                cpa16(sb + BXF(0) + c * 256 + u * 16,
                      (const char*)(xb + (size_t)c * KL + (size_t)kbase * 64) + u * 16);
            }
        CP_COMMIT();
    }

    const int rowA = lane & 15, colA = (lane >> 4) * 8;
    const int rowB = lane & 15, colB = (lane >> 4) * 8;

    for (int ki = 0; ki < G; ++ki) {
        const int kcol = kbase + ki;
        if (ki + 1 < G) {          // prefetch next fp32 tile
            int e = tid;
            #pragma unroll
            for (int it = 0; it < 2; ++it, e += 640)
                if (e < 1024) {
                    int c = e >> 4, u = e & 15;
                    cpa16(sb + BXF((ki + 1) & 1) + c * 256 + u * 16,
                          (const char*)(xb + (size_t)c * KL + (size_t)(kcol + 1) * 64) + u * 16);
                }
            CP_COMMIT();
            CP_WAIT1();
        } else {
            CP_WAIT0();
        }
        __syncthreads();           // fp32 tile ki visible (and W on first iter)

        // convert fp32 -> bf16 hi/lo planes
        {
            const float4* fs = (const float4*)(smem + BXF(ki & 1));
            char* bh = smem + BXB(ki & 1);
            int e = tid;
            #pragma unroll
            for (int it = 0; it < 2; ++it, e += 640)
                if (e < 1024) {
                    int c = e >> 4, q = e & 15;
                    float4 v = fs[c * 16 + q];
                    __nv_bfloat16 h0, l0, h1, l1, h2, l2, h3, l3;
                    split2(v.x, h0, l0); split2(v.y, h1, l1);
                    split2(v.z, h2, l2); split2(v.w, h3, l3);
                    uint2 ph, pl;
                    ph.x = (uint32_t)__bfloat16_as_ushort(h0) | ((uint32_t)__bfloat16_as_ushort(h1) << 16);
                    ph.y = (uint32_t)__bfloat16_as_ushort(h2) | ((uint32_t)__bfloat16_as_ushort(h3) << 16);
                    pl.x = (uint32_t)__bfloat16_as_ushort(l0) | ((uint32_t)__bfloat16_as_ushort(l1) << 16);
                    pl.y = (uint32_t)__bfloat16_as_ushort(l2) | ((uint32_t)__bfloat16_as_ushort(l3) << 16);
                    *(uint2*)(bh + c * 144 + q * 8) = ph;
                    *(uint2*)(bh + 9216 + c * 144 + q * 8) = pl;
                }
        }
        __syncthreads();

        float acc[8][4];
        #pragma unroll
        for (int j = 0; j < 8; ++j)
            #pragma unroll
            for (int q = 0; q < 4; ++q) acc[j][q] = 0.f;

        const uint32_t xbase = sb + BXB(ki & 1);
        #pragma unroll
        for (int c0 = 0; c0 < 64; c0 += 16) {
            uint32_t ah[4], al[4];
            uint32_t ra = sb + BW_H + (uint32_t)(((w * 16 + rowA) * 72 + c0 + colA) * 2);
            ldsm4(ah, ra);
            ldsm4(al, ra + (BW_L - BW_H));
            #pragma unroll
            for (int p = 0; p < 4; ++p) {
                uint32_t bh[4], bl[4];
                uint32_t rb = xbase + (uint32_t)(((c0 + rowB) * 72 + p * 16 + colB) * 2);
                ldsm4t(bh, rb);
                ldsm4t(bl, rb + 9216);
                #pragma unroll
                for (int jj = 0; jj < 2; ++jj) {
                    float* d = acc[p * 2 + jj];
                    mma16816(d, ah, &bh[jj * 2]);
                    mma16816(d, ah, &bl[jj * 2]);
                    mma16816(d, al, &bh[jj * 2]);
                }
            }
        }

        // epilogue
        #pragma unroll
        for (int rsel = 0; rsel < 2; ++rsel) {
            const int m = w * 16 + (lane >> 2) + rsel * 8;
            const int t = m >> 6, o = m & 63;
            if (t == 0) {
                const float bo = bias[o];
                float* op = out + ((size_t)b * 64 + o) * KL + (size_t)kcol * 64;
                #pragma unroll
                for (int n8 = 0; n8 < 8; ++n8) {
                    int l = n8 * 8 + (lane & 3) * 2;
                    *(float2*)(op + l) = make_float2(acc[n8][rsel * 2] + bo,
                                                     acc[n8][rsel * 2 + 1] + bo);
                }
            } else {
                const size_t rb2 = ((((size_t)b * 4 + (t - 1)) * 64 + o) * K_DIM + kcol) * 64;
                uint32_t* Uhp = (uint32_t*)(g_Uh + rb2);
                uint32_t* Ulp = (uint32_t*)(g_Ul + rb2);
                #pragma unroll
                for (int n8 = 0; n8 < 8; ++n8) {
                    int l = n8 * 8 + (lane & 3) * 2;
                    __nv_bfloat16 h0, l0, h1, l1;
                    split2(acc[n8][rsel * 2], h0, l0);
                    split2(acc[n8][rsel * 2 + 1], h1, l1);
                    Uhp[l >> 1] = (uint32_t)__bfloat16_as_ushort(h0) |
                                  ((uint32_t)__bfloat16_as_ushort(h1) << 16);
                    Ulp[l >> 1] = (uint32_t)__bfloat16_as_ushort(l0) |
                                  ((uint32_t)__bfloat16_as_ushort(l1) << 16);
                }
            }
        }
    }
}

// ---------------------------------------------------------------- Stage C
// Block (o-pair, b): out[b,o,j,l] += sum_t sum_k M_t[j,k] * U[b,t,o,k,l]
// o-tile = 2 (A staged once for both). cp.async double-buffered.
#define C_AH 0
#define C_AL 36864
#define C_BH 73728          // + oi*9216
#define C_BL 92160          // + oi*9216
#define CBUF 110592
#define C_SMEM (2 * CBUF)

__global__ __launch_bounds__(512)
void diffuse_mma(float* __restrict__ out) {
    extern __shared__ __align__(16) char smem[];
    const int tid = threadIdx.x, lane = tid & 31, w = tid >> 5;
    const int b = blockIdx.y, o0 = blockIdx.x * 2;
    const uint32_t sb = smem_u32(smem);

    float acc[2][8][4];
    #pragma unroll
    for (int oi = 0; oi < 2; ++oi)
        #pragma unroll
        for (int j = 0; j < 8; ++j)
            #pragma unroll
            for (int q = 0; q < 4; ++q) acc[oi][j][q] = 0.f;

    const int rowA = lane & 15, colA = (lane >> 4) * 8;
    const int rowB = lane & 15, colB = (lane >> 4) * 8;

    auto stage = [&](int s, int buf) {
        const int t = s >> 2, kc = s & 3;
        const char* Mh = (const char*)(g_Mh + ((size_t)(b * 4 + t) << 16));
        const char* Ml = (const char*)(g_Ml + ((size_t)(b * 4 + t) << 16));
        const uint32_t base = sb + buf * CBUF;
        // A: 2 planes x 256 rows x 8 x 16B = 4096 xfers
        #pragma unroll
        for (int it = 0; it < 8; ++it) {
            int e = tid + it * 512;
            int pl = e >> 11, r = (e >> 3) & 255, u = e & 7;
            const char* src = (pl ? Ml : Mh) + r * 512 + kc * 128 + u * 16;
            cpa16(base + (pl ? C_AL : C_AH) + r * 144 + u * 16, src);
        }
        // B: 2 oi x 2 planes x 64 rows x 8 x 16B = 2048 xfers, zfill pad
        #pragma unroll
        for (int it = 0; it < 4; ++it) {
            int e = tid + it * 512;
            int oi = e >> 10, rem = e & 1023;
            int pl = rem >> 9, r = (rem >> 3) & 63, u = rem & 7;
            int kg = kc * 64 + r;
            int sz = (kg < K_DIM) ? 16 : 0;
            const char* Ub = (const char*)(pl ? g_Ul : g_Uh) +
                ((((size_t)b * 4 + t) * 64 + o0 + oi) * K_DIM) * 128;
            size_t so = (size_t)((kg < K_DIM) ? kg : 0) * 128 + u * 16;
            cpa16z(base + (pl ? C_BL : C_BH) + oi * 9216 + r * 144 + u * 16, Ub + so, sz);
        }
        CP_COMMIT();
    };

    stage(0, 0);
    for (int s = 0; s < 16; ++s) {
        if (s + 1 < 16) { stage(s + 1, (s + 1) & 1); CP_WAIT1(); }
        else            { CP_WAIT0(); }
        __syncthreads();
        const uint32_t base = sb + (s & 1) * CBUF;
        #pragma unroll
        for (int c0 = 0; c0 < 64; c0 += 16) {
            uint32_t ah[4], al[4];
            uint32_t ra = base + C_AH + (uint32_t)(((w * 16 + rowA) * 72 + c0 + colA) * 2);
            ldsm4(ah, ra);
            ldsm4(al, ra + (C_AL - C_AH));
            #pragma unroll
            for (int oi = 0; oi < 2; ++oi) {
                #pragma unroll
                for (int p = 0; p < 4; ++p) {
                    uint32_t bh[4], bl[4];
                    uint32_t rb = base + C_BH + oi * 9216 +
                                  (uint32_t)(((c0 + rowB) * 72 + p * 16 + colB) * 2);
                    ldsm4t(bh, rb);
                    ldsm4t(bl, rb + (C_BL - C_BH));
                    #pragma unroll
                    for (int jj = 0; jj < 2; ++jj) {
                        float* d = acc[oi][p * 2 + jj];
                        mma16816(d, ah, &bh[jj * 2]);
                        mma16816(d, ah, &bl[jj * 2]);
                        mma16816(d, al, &bh[jj * 2]);
                    }
                }
            }
        }
        __syncthreads();
    }

    // epilogue: RMW onto out (both o's)
    #pragma unroll
    for (int oi = 0; oi < 2; ++oi) {
        float* ob = out + ((size_t)b * 64 + o0 + oi) * KL;
        #pragma unroll
        for (int rsel = 0; rsel < 2; ++rsel) {
            const int j = w * 16 + (lane >> 2) + rsel * 8;
            if (j < K_DIM) {
                float* op = ob + (size_t)j * 64;
                #pragma unroll
                for (int n8 = 0; n8 < 8; ++n8) {
                    int l = n8 * 8 + (lane & 3) * 2;
                    float2 u = *(float2*)(op + l);
                    u.x += acc[oi][n8][rsel * 2];
                    u.y += acc[oi][n8][rsel * 2 + 1];
                    *(float2*)(op + l) = u;
                }
            }
        }
    }
}

// ----------------------------------------------------------------
extern "C" void kernel_launch(void* const* d_in, const int* in_sizes, int n_in,
                              void* d_out, int out_size) {
    (void)in_sizes; (void)n_in; (void)out_size;
    const float* x    = (const float*)d_in[0];
    const float* a0   = (const float*)d_in[1];
    const float* a1   = (const float*)d_in[2];
    const float* W    = (const float*)d_in[3];
    const float* bias = (const float*)d_in[4];
    float* out        = (float*)d_out;

    cudaFuncSetAttribute(chanmix_mma, cudaFuncAttributeMaxDynamicSharedMemorySize, B_SMEM);
    cudaFuncSetAttribute(diffuse_mma, cudaFuncAttributeMaxDynamicSharedMemorySize, C_SMEM);

    {
        dim3 grid((K_DIM + 31) / 32, (K_DIM + 31) / 32, 2 * B_DIM);
        dim3 block(16, 16);
        square_kernel<<<grid, block>>>(a0, a1);
    }
    splitM_kernel<<<16384, 256>>>(a0, a1);
    splitW_kernel<<<80, 256>>>(W);
    {
        dim3 grid((K_DIM + KGRP - 1) / KGRP, B_DIM);   // 52 x 16
        chanmix_mma<<<grid, 640, B_SMEM>>>(x, bias, out);
    }
    {
        dim3 grid(C_DIM / 2, B_DIM);   // 32 x 16
        diffuse_mma<<<grid, 512, C_SMEM>>>(out);
    }
}

// round 11
// speedup vs baseline: 2.0961x; 1.1687x over previous
#include <cuda_runtime.h>
#include <cuda_bf16.h>
#include <cstdint>

#define B_DIM 16
#define C_DIM 64
#define K_DIM 207
#define L_DIM 64
#define KL    13248
#define C_IN  320
#define KSQ   (K_DIM * K_DIM)

// scratch
__device__ __nv_bfloat16 g_Mh[(size_t)B_DIM * 4 * 256 * 256];   // padded split M_t (t:0=A0,1=A0^2,2=A1,3=A1^2)
__device__ __nv_bfloat16 g_Ml[(size_t)B_DIM * 4 * 256 * 256];
__device__ __nv_bfloat16 g_Wh[320 * 64];                        // split W
__device__ __nv_bfloat16 g_Wl[320 * 64];
__device__ __nv_bfloat16 g_Uh[(size_t)B_DIM * 4 * C_DIM * K_DIM * L_DIM];  // [b][t][o][k][l]
__device__ __nv_bfloat16 g_Ul[(size_t)B_DIM * 4 * C_DIM * K_DIM * L_DIM];

__device__ __forceinline__ uint32_t smem_u32(const void* p) {
    uint32_t a;
    asm("{ .reg .u64 t; cvta.to.shared.u64 t, %1; cvt.u32.u64 %0, t; }" : "=r"(a) : "l"(p));
    return a;
}
__device__ __forceinline__ void split2(float v, __nv_bfloat16& h, __nv_bfloat16& l) {
    h = __float2bfloat16(v);
    l = __float2bfloat16(v - __bfloat162float(h));
}
__device__ __forceinline__ void ldsm4(uint32_t* r, uint32_t addr) {
    asm volatile("ldmatrix.sync.aligned.m8n8.x4.shared.b16 {%0,%1,%2,%3}, [%4];"
                 : "=r"(r[0]), "=r"(r[1]), "=r"(r[2]), "=r"(r[3]) : "r"(addr));
}
__device__ __forceinline__ void ldsm4t(uint32_t* r, uint32_t addr) {
    asm volatile("ldmatrix.sync.aligned.m8n8.x4.trans.shared.b16 {%0,%1,%2,%3}, [%4];"
                 : "=r"(r[0]), "=r"(r[1]), "=r"(r[2]), "=r"(r[3]) : "r"(addr));
}
__device__ __forceinline__ void mma16816(float* d, const uint32_t* a, const uint32_t* b) {
    asm volatile(
        "mma.sync.aligned.m16n8k16.row.col.f32.bf16.bf16.f32 "
        "{%0,%1,%2,%3}, {%4,%5,%6,%7}, {%8,%9}, {%0,%1,%2,%3};"
        : "+f"(d[0]), "+f"(d[1]), "+f"(d[2]), "+f"(d[3])
        : "r"(a[0]), "r"(a[1]), "r"(a[2]), "r"(a[3]), "r"(b[0]), "r"(b[1]));
}
__device__ __forceinline__ void cpa16(uint32_t dst, const void* src) {
    asm volatile("cp.async.cg.shared.global [%0], [%1], 16;" :: "r"(dst), "l"(src));
}
__device__ __forceinline__ void cpa16z(uint32_t dst, const void* src, int sz) {
    asm volatile("cp.async.cg.shared.global [%0], [%1], 16, %2;" :: "r"(dst), "l"(src), "r"(sz));
}
#define CP_COMMIT() asm volatile("cp.async.commit_group;" ::: "memory")
#define CP_WAIT0()  asm volatile("cp.async.wait_group 0;" ::: "memory")
#define CP_WAIT1()  asm volatile("cp.async.wait_group 1;" ::: "memory")

// ---------------------------------------------------------------- split A0/A1 into padded planes (slots 0, 2)
__global__ __launch_bounds__(256)
void splitM_kernel(const float* __restrict__ a0, const float* __restrict__ a1) {
    size_t e = (size_t)blockIdx.x * 256 + threadIdx.x;   // 2*16*65536 total
    int k = (int)(e & 255), j = (int)((e >> 8) & 255);
    int which = (int)((e >> 16) & 1), b = (int)(e >> 17);
    float v = 0.f;
    if (j < K_DIM && k < K_DIM) {
        const float* M = (which ? a1 : a0) + (size_t)b * KSQ;
        v = M[(size_t)j * K_DIM + k];
    }
    __nv_bfloat16 h, l; split2(v, h, l);
    size_t idx = (((size_t)(b * 4 + which * 2)) << 16) + ((size_t)j << 8) + k;
    g_Mh[idx] = h; g_Ml[idx] = l;
}

__global__ __launch_bounds__(256)
void splitW_kernel(const float* __restrict__ W) {
    int e = blockIdx.x * 256 + threadIdx.x;
    if (e < 320 * 64) {
        int m = e >> 6, c = e & 63;
        int t = m >> 6, o = m & 63;
        float v = W[(size_t)o * C_IN + t * 64 + c];
        __nv_bfloat16 h, l; split2(v, h, l);
        g_Wh[e] = h; g_Wl[e] = l;
    }
}

// ---------------------------------------------------------------- square via MMA: slot t+1 = (slot t)^2
// Block (nhalf, which, b): D[j, n] = sum_m A[j,m] A[m,n], n in [nhalf*128, +128)
#define SQ_AH 0
#define SQ_AL 36864
#define SQ_BH 73728
#define SQ_BL 91136
#define SQ_SMEM 108544

__global__ __launch_bounds__(512)
void square_mma() {
    extern __shared__ __align__(16) char smem[];
    const int tid = threadIdx.x, lane = tid & 31, w = tid >> 5;
    const int nh = blockIdx.x, which = blockIdx.y, b = blockIdx.z;
    const int tslot = which * 2;
    const uint32_t sb = smem_u32(smem);
    const char* Mh = (const char*)(g_Mh + ((size_t)(b * 4 + tslot) << 16));
    const char* Ml = (const char*)(g_Ml + ((size_t)(b * 4 + tslot) << 16));

    float acc[16][4];
    #pragma unroll
    for (int i = 0; i < 16; ++i)
        #pragma unroll
        for (int q = 0; q < 4; ++q) acc[i][q] = 0.f;

    const int rowA = lane & 15, colA = (lane >> 4) * 8;
    const int rowB = lane & 15, colB = (lane >> 4) * 8;

    for (int kc = 0; kc < 4; ++kc) {
        // A-op: 256 rows x 64 cols (both planes), row stride 144B
        #pragma unroll
        for (int it = 0; it < 8; ++it) {
            int e = tid + it * 512;
            int pl = e >> 11, rem = e & 2047;
            int r = rem >> 3, u = rem & 7;
            const char* src = (pl ? Ml : Mh) + r * 512 + kc * 128 + u * 16;
            cpa16(sb + (pl ? SQ_AL : SQ_AH) + r * 144 + u * 16, src);
        }
        // B-op: 64 m-rows x 128 n-cols (both planes), row stride 272B
        #pragma unroll
        for (int it = 0; it < 4; ++it) {
            int e = tid + it * 512;
            int pl = e >> 10, rem = e & 1023;
            int r = rem >> 4, u = rem & 15;
            const char* src = (pl ? Ml : Mh) + (kc * 64 + r) * 512 + nh * 256 + u * 16;
            cpa16(sb + (pl ? SQ_BL : SQ_BH) + r * 272 + u * 16, src);
        }
        CP_COMMIT();
        CP_WAIT0();
        __syncthreads();

        #pragma unroll
        for (int c0 = 0; c0 < 64; c0 += 16) {
            uint32_t ah[4], al[4];
            uint32_t ra = sb + SQ_AH + (uint32_t)(((w * 16 + rowA) * 72 + c0 + colA) * 2);
            ldsm4(ah, ra);
            ldsm4(al, ra + (SQ_AL - SQ_AH));
            #pragma unroll
            for (int p = 0; p < 8; ++p) {
                uint32_t bh[4], bl[4];
                uint32_t rb = sb + SQ_BH + (uint32_t)(((c0 + rowB) * 136 + p * 16 + colB) * 2);
                ldsm4t(bh, rb);
                ldsm4t(bl, rb + (SQ_BL - SQ_BH));
                #pragma unroll
                for (int jj = 0; jj < 2; ++jj) {
                    float* d = acc[p * 2 + jj];
                    mma16816(d, ah, &bh[jj * 2]);
                    mma16816(d, ah, &bl[jj * 2]);
                    mma16816(d, al, &bh[jj * 2]);
                }
            }
        }
        __syncthreads();
    }

    // epilogue: split and write slot tslot+1 (rows >=207 are zero by construction)
    uint32_t* Dh = (uint32_t*)(g_Mh + ((size_t)(b * 4 + tslot + 1) << 16));
    uint32_t* Dl = (uint32_t*)(g_Ml + ((size_t)(b * 4 + tslot + 1) << 16));
    #pragma unroll
    for (int rsel = 0; rsel < 2; ++rsel) {
        const int j = w * 16 + (lane >> 2) + rsel * 8;
        #pragma unroll
        for (int i = 0; i < 16; ++i) {
            int n = nh * 128 + i * 8 + (lane & 3) * 2;
            __nv_bfloat16 h0, l0, h1, l1;
            split2(acc[i][rsel * 2], h0, l0);
            split2(acc[i][rsel * 2 + 1], h1, l1);
            Dh[(j * 256 + n) >> 1] = (uint32_t)__bfloat16_as_ushort(h0) |
                                     ((uint32_t)__bfloat16_as_ushort(h1) << 16);
            Dl[(j * 256 + n) >> 1] = (uint32_t)__bfloat16_as_ushort(l0) |
                                     ((uint32_t)__bfloat16_as_ushort(l1) << 16);
        }
    }
}

// ---------------------------------------------------------------- Stage B
#define BW_H 0
#define BW_L 46080
#define BXF(buf)  (92160 + (buf) * 16384)
#define BXB(buf)  (124928 + (buf) * 18432)
#define B_SMEM 161792
#define KGRP 8

__global__ __launch_bounds__(640)
void chanmix_mma(const float* __restrict__ x, const float* __restrict__ bias,
                 float* __restrict__ out) {
    extern __shared__ __align__(16) char smem[];
    const int tid = threadIdx.x, lane = tid & 31, w = tid >> 5;
    const int b = blockIdx.y;
    const int kbase = blockIdx.x * KGRP;
    const int G = (kbase + KGRP <= K_DIM) ? KGRP : (K_DIM - kbase);
    const uint32_t sb = smem_u32(smem);
    const float* xb = x + (size_t)b * C_DIM * KL;

    #pragma unroll
    for (int it = 0; it < 4; ++it) {
        int e = tid + it * 640;
        if (e < 2560) {
            int r = e >> 3, u = e & 7;
            cpa16(sb + BW_H + r * 144 + u * 16, (const char*)g_Wh + r * 128 + u * 16);
            cpa16(sb + BW_L + r * 144 + u * 16, (const char*)g_Wl + r * 128 + u * 16);
        }
    }
    CP_COMMIT();

    {
        int e = tid;
        #pragma unroll
        for (int it = 0; it < 2; ++it, e += 640)
            if (e < 1024) {
                int c = e >> 4, u = e & 15;
                cpa16(sb + BXF(0) + c * 256 + u * 16,
                      (const char*)(xb + (size_t)c * KL + (size_t)kbase * 64) + u * 16);
            }
        CP_COMMIT();
    }

    const int rowA = lane & 15, colA = (lane >> 4) * 8;
    const int rowB = lane & 15, colB = (lane >> 4) * 8;

    for (int ki = 0; ki < G; ++ki) {
        const int kcol = kbase + ki;
        if (ki + 1 < G) {
            int e = tid;
            #pragma unroll
            for (int it = 0; it < 2; ++it, e += 640)
                if (e < 1024) {
                    int c = e >> 4, u = e & 15;
                    cpa16(sb + BXF((ki + 1) & 1) + c * 256 + u * 16,
                          (const char*)(xb + (size_t)c * KL + (size_t)(kcol + 1) * 64) + u * 16);
                }
            CP_COMMIT();
            CP_WAIT1();
        } else {
            CP_WAIT0();
        }
        __syncthreads();

        {
            const float4* fs = (const float4*)(smem + BXF(ki & 1));
            char* bh = smem + BXB(ki & 1);
            int e = tid;
            #pragma unroll
            for (int it = 0; it < 2; ++it, e += 640)
                if (e < 1024) {
                    int c = e >> 4, q = e & 15;
                    float4 v = fs[c * 16 + q];
                    __nv_bfloat16 h0, l0, h1, l1, h2, l2, h3, l3;
                    split2(v.x, h0, l0); split2(v.y, h1, l1);
                    split2(v.z, h2, l2); split2(v.w, h3, l3);
                    uint2 ph, pl;
                    ph.x = (uint32_t)__bfloat16_as_ushort(h0) | ((uint32_t)__bfloat16_as_ushort(h1) << 16);
                    ph.y = (uint32_t)__bfloat16_as_ushort(h2) | ((uint32_t)__bfloat16_as_ushort(h3) << 16);
                    pl.x = (uint32_t)__bfloat16_as_ushort(l0) | ((uint32_t)__bfloat16_as_ushort(l1) << 16);
                    pl.y = (uint32_t)__bfloat16_as_ushort(l2) | ((uint32_t)__bfloat16_as_ushort(l3) << 16);
                    *(uint2*)(bh + c * 144 + q * 8) = ph;
                    *(uint2*)(bh + 9216 + c * 144 + q * 8) = pl;
                }
        }
        __syncthreads();

        float acc[8][4];
        #pragma unroll
        for (int j = 0; j < 8; ++j)
            #pragma unroll
            for (int q = 0; q < 4; ++q) acc[j][q] = 0.f;

        const uint32_t xbase = sb + BXB(ki & 1);
        #pragma unroll
        for (int c0 = 0; c0 < 64; c0 += 16) {
            uint32_t ah[4], al[4];
            uint32_t ra = sb + BW_H + (uint32_t)(((w * 16 + rowA) * 72 + c0 + colA) * 2);
            ldsm4(ah, ra);
            ldsm4(al, ra + (BW_L - BW_H));
            #pragma unroll
            for (int p = 0; p < 4; ++p) {
                uint32_t bh[4], bl[4];
                uint32_t rb = xbase + (uint32_t)(((c0 + rowB) * 72 + p * 16 + colB) * 2);
                ldsm4t(bh, rb);
                ldsm4t(bl, rb + 9216);
                #pragma unroll
                for (int jj = 0; jj < 2; ++jj) {
                    float* d = acc[p * 2 + jj];
                    mma16816(d, ah, &bh[jj * 2]);
                    mma16816(d, ah, &bl[jj * 2]);
                    mma16816(d, al, &bh[jj * 2]);
                }
            }
        }

        #pragma unroll
        for (int rsel = 0; rsel < 2; ++rsel) {
            const int m = w * 16 + (lane >> 2) + rsel * 8;
            const int t = m >> 6, o = m & 63;
            if (t == 0) {
                const float bo = bias[o];
                float* op = out + ((size_t)b * 64 + o) * KL + (size_t)kcol * 64;
                #pragma unroll
                for (int n8 = 0; n8 < 8; ++n8) {
                    int l = n8 * 8 + (lane & 3) * 2;
                    *(float2*)(op + l) = make_float2(acc[n8][rsel * 2] + bo,
                                                     acc[n8][rsel * 2 + 1] + bo);
                }
            } else {
                const size_t rb2 = ((((size_t)b * 4 + (t - 1)) * 64 + o) * K_DIM + kcol) * 64;
                uint32_t* Uhp = (uint32_t*)(g_Uh + rb2);
                uint32_t* Ulp = (uint32_t*)(g_Ul + rb2);
                #pragma unroll
                for (int n8 = 0; n8 < 8; ++n8) {
                    int l = n8 * 8 + (lane & 3) * 2;
                    __nv_bfloat16 h0, l0, h1, l1;
                    split2(acc[n8][rsel * 2], h0, l0);
                    split2(acc[n8][rsel * 2 + 1], h1, l1);
                    Uhp[l >> 1] = (uint32_t)__bfloat16_as_ushort(h0) |
                                  ((uint32_t)__bfloat16_as_ushort(h1) << 16);
                    Ulp[l >> 1] = (uint32_t)__bfloat16_as_ushort(l0) |
                                  ((uint32_t)__bfloat16_as_ushort(l1) << 16);
                }
            }
        }
    }
}

// ---------------------------------------------------------------- Stage C
// A staged 208 j-rows only; warps >= 13 skip MMA; last k-chunk runs c0<16.
#define C_AH 0
#define C_AL 29952
#define C_BH 59904          // + oi*9216
#define C_BL 78336          // + oi*9216
#define CBUF 96768
#define C_SMEM (2 * CBUF)

__global__ __launch_bounds__(512)
void diffuse_mma(float* __restrict__ out) {
    extern __shared__ __align__(16) char smem[];
    const int tid = threadIdx.x, lane = tid & 31, w = tid >> 5;
    const int b = blockIdx.y, o0 = blockIdx.x * 2;
    const uint32_t sb = smem_u32(smem);

    float acc[2][8][4];
    #pragma unroll
    for (int oi = 0; oi < 2; ++oi)
        #pragma unroll
        for (int j = 0; j < 8; ++j)
            #pragma unroll
            for (int q = 0; q < 4; ++q) acc[oi][j][q] = 0.f;

    const int rowA = lane & 15, colA = (lane >> 4) * 8;
    const int rowB = lane & 15, colB = (lane >> 4) * 8;

    auto stage = [&](int s, int buf) {
        const int t = s >> 2, kc = s & 3;
        const char* Mh = (const char*)(g_Mh + ((size_t)(b * 4 + t) << 16));
        const char* Ml = (const char*)(g_Ml + ((size_t)(b * 4 + t) << 16));
        const uint32_t base = sb + buf * CBUF;
        // A: 2 planes x 208 rows x 8 x 16B = 3328 xfers
        #pragma unroll
        for (int it = 0; it < 7; ++it) {
            int e = tid + it * 512;
            if (e < 3328) {
                int pl = e / 1664, rem = e - pl * 1664;
                int r = rem >> 3, u = rem & 7;
                const char* src = (pl ? Ml : Mh) + r * 512 + kc * 128 + u * 16;
                cpa16(base + (pl ? C_AL : C_AH) + r * 144 + u * 16, src);
            }
        }
        // B: 2 oi x 2 planes x 64 rows x 8 x 16B = 2048 xfers, zfill pad
        #pragma unroll
        for (int it = 0; it < 4; ++it) {
            int e = tid + it * 512;
            int oi = e >> 10, rem = e & 1023;
            int pl = rem >> 9, r = (rem >> 3) & 63, u = rem & 7;
            int kg = kc * 64 + r;
            int sz = (kg < K_DIM) ? 16 : 0;
            const char* Ub = (const char*)(pl ? g_Ul : g_Uh) +
                ((((size_t)b * 4 + t) * 64 + o0 + oi) * K_DIM) * 128;
            size_t so = (size_t)((kg < K_DIM) ? kg : 0) * 128 + u * 16;
            cpa16z(base + (pl ? C_BL : C_BH) + oi * 9216 + r * 144 + u * 16, Ub + so, sz);
        }
        CP_COMMIT();
    };

    stage(0, 0);
    for (int s = 0; s < 16; ++s) {
        if (s + 1 < 16) { stage(s + 1, (s + 1) & 1); CP_WAIT1(); }
        else            { CP_WAIT0(); }
        __syncthreads();
        const uint32_t base = sb + (s & 1) * CBUF;
        if (w < 13) {
            const int c0max = ((s & 3) == 3) ? 16 : 64;
            for (int c0 = 0; c0 < c0max; c0 += 16) {
                uint32_t ah[4], al[4];
                uint32_t ra = base + C_AH + (uint32_t)(((w * 16 + rowA) * 72 + c0 + colA) * 2);
                ldsm4(ah, ra);
                ldsm4(al, ra + (C_AL - C_AH));
                #pragma unroll
                for (int oi = 0; oi < 2; ++oi) {
                    #pragma unroll
                    for (int p = 0; p < 4; ++p) {
                        uint32_t bh[4], bl[4];
                        uint32_t rb = base + C_BH + oi * 9216 +
                                      (uint32_t)(((c0 + rowB) * 72 + p * 16 + colB) * 2);
                        ldsm4t(bh, rb);
                        ldsm4t(bl, rb + (C_BL - C_BH));
                        #pragma unroll
                        for (int jj = 0; jj < 2; ++jj) {
                            float* d = acc[oi][p * 2 + jj];
                            mma16816(d, ah, &bh[jj * 2]);
                            mma16816(d, ah, &bl[jj * 2]);
                            mma16816(d, al, &bh[jj * 2]);
                        }
                    }
                }
            }
        }
        __syncthreads();
    }

    #pragma unroll
    for (int oi = 0; oi < 2; ++oi) {
        float* ob = out + ((size_t)b * 64 + o0 + oi) * KL;
        #pragma unroll
        for (int rsel = 0; rsel < 2; ++rsel) {
            const int j = w * 16 + (lane >> 2) + rsel * 8;
            if (j < K_DIM) {
                float* op = ob + (size_t)j * 64;
                #pragma unroll
                for (int n8 = 0; n8 < 8; ++n8) {
                    int l = n8 * 8 + (lane & 3) * 2;
                    float2 u = *(float2*)(op + l);
                    u.x += acc[oi][n8][rsel * 2];
                    u.y += acc[oi][n8][rsel * 2 + 1];
                    *(float2*)(op + l) = u;
                }
            }
        }
    }
}

// ----------------------------------------------------------------
extern "C" void kernel_launch(void* const* d_in, const int* in_sizes, int n_in,
                              void* d_out, int out_size) {
    (void)in_sizes; (void)n_in; (void)out_size;
    const float* x    = (const float*)d_in[0];
    const float* a0   = (const float*)d_in[1];
    const float* a1   = (const float*)d_in[2];
    const float* W    = (const float*)d_in[3];
    const float* bias = (const float*)d_in[4];
    float* out        = (float*)d_out;

    cudaFuncSetAttribute(square_mma, cudaFuncAttributeMaxDynamicSharedMemorySize, SQ_SMEM);
    cudaFuncSetAttribute(chanmix_mma, cudaFuncAttributeMaxDynamicSharedMemorySize, B_SMEM);
    cudaFuncSetAttribute(diffuse_mma, cudaFuncAttributeMaxDynamicSharedMemorySize, C_SMEM);

    splitM_kernel<<<8192, 256>>>(a0, a1);
    splitW_kernel<<<80, 256>>>(W);
    {
        dim3 grid(2, 2, B_DIM);    // nhalf x which x b
        square_mma<<<grid, 512, SQ_SMEM>>>();
    }
    {
        dim3 grid((K_DIM + KGRP - 1) / KGRP, B_DIM);   // 26 x 16
        chanmix_mma<<<grid, 640, B_SMEM>>>(x, bias, out);
    }
    {
        dim3 grid(C_DIM / 2, B_DIM);   // 32 x 16
        diffuse_mma<<<grid, 512, C_SMEM>>>(out);
    }
}